// round 3
// baseline (speedup 1.0000x reference)
#include <cuda_runtime.h>
#include <math.h>

#define NN   50000
#define NE   800000
#define FIN  256
#define HD   128
#define EDIM 60
#define NEG_SLOPE 0.2f
#define SCANB 49                 // ceil(NN/1024)
#define G1BLK ((NN+127)/128)     // 391 gemm blocks
#define EDBLK (NE/8)             // 100000 edgedot blocks (warp/edge, 8 warps/blk)
#define ALPHABLK ((NN*32)/256)   // 6250

// ---------------- scratch ----------------
__device__ float d_h [NN*HD];
__device__ float d_g [NN*HD];
__device__ float d_z [NN*HD];
__device__ float d_as[NN], d_ad[NN];
__device__ float d_aE1[NE], d_aE2[NE];
__device__ float d_esum1[NN], d_esum2[NN];
__device__ int   d_deg[NN];
__device__ int   d_rows[NN];      // inclusive scan of deg, partial within 1024-block
__device__ int   d_bsum[SCANB];
__device__ int   d_boff[SCANB];   // exclusive scan of bsum
__device__ int   d_cursor[NN];
__device__ int   d_csr[NE];
__device__ float d_wvec1[EDIM], d_wvec2[EDIM];

__device__ __forceinline__ float lrelu(float v){ return v > 0.f ? v : NEG_SLOPE*v; }
// global CSR row start reconstructed from partial scan (no finalize pass needed)
__device__ __forceinline__ int startOf(int d){
    return (d == 0) ? 0 : d_rows[d-1] + d_boff[(d-1)>>10];
}

// ---------------- K_pre: zero accumulators + wvec = We @ a_edge ----------------
__global__ void k_pre(const float* __restrict__ We1, const float* __restrict__ ae1,
                      const float* __restrict__ We2, const float* __restrict__ ae2) {
    int i = blockIdx.x*blockDim.x + threadIdx.x;
    if (i < NN) { d_deg[i]=0; d_esum1[i]=0.f; d_esum2[i]=0.f; d_cursor[i]=0; }
    if (blockIdx.x == 0 && threadIdx.x < EDIM) {
        int j = threadIdx.x;
        float s1=0.f, s2=0.f;
        for (int c=0;c<HD;c++){ s1 += We1[j*HD+c]*ae1[c]; s2 += We2[j*HD+c]*ae2[c]; }
        d_wvec1[j]=s1; d_wvec2[j]=s2;
    }
}

// ---------------- SGEMM body: C[M,128]=A[M,K]@B[K,128], double-buffered --------
__device__ __forceinline__ void sgemm_body(const float* __restrict__ A,
                                           const float* __restrict__ B,
                                           float* __restrict__ C,
                                           int M, int K, int bx) {
    __shared__ float As[2][8][128];
    __shared__ float Bs[2][8][128];
    int tid  = threadIdx.x;
    int tcol = tid & 15, trow = tid >> 4;
    int row0 = bx * 128;
    int aRow = tid >> 1, aCol = (tid & 1) * 4;
    int bRow = tid >> 5, bCol = (tid & 31) * 4;
    int ar = row0 + aRow;
    float acc[8][8];
    #pragma unroll
    for (int i=0;i<8;i++)
        #pragma unroll
        for (int j=0;j<8;j++) acc[i][j]=0.f;

    // preload tile 0
    float4 a4 = make_float4(0.f,0.f,0.f,0.f);
    if (ar < M) a4 = *(const float4*)&A[(size_t)ar*K + aCol];
    float4 b4 = *(const float4*)&B[(size_t)bRow*128 + bCol];
    As[0][aCol+0][aRow]=a4.x; As[0][aCol+1][aRow]=a4.y;
    As[0][aCol+2][aRow]=a4.z; As[0][aCol+3][aRow]=a4.w;
    *(float4*)&Bs[0][bRow][bCol] = b4;
    __syncthreads();

    int buf = 0;
    for (int k0=0; k0<K; k0+=8) {
        int nxt = k0 + 8;
        bool more = nxt < K;
        float4 an = make_float4(0.f,0.f,0.f,0.f), bn;
        if (more) {
            if (ar < M) an = *(const float4*)&A[(size_t)ar*K + nxt + aCol];
            bn = *(const float4*)&B[(size_t)(nxt+bRow)*128 + bCol];
        }
        #pragma unroll
        for (int k=0;k<8;k++){
            float4 a0 = *(const float4*)&As[buf][k][trow*8];
            float4 a1 = *(const float4*)&As[buf][k][trow*8+4];
            float4 b0 = *(const float4*)&Bs[buf][k][tcol*8];
            float4 b1 = *(const float4*)&Bs[buf][k][tcol*8+4];
            float ar_[8] = {a0.x,a0.y,a0.z,a0.w,a1.x,a1.y,a1.z,a1.w};
            float br_[8] = {b0.x,b0.y,b0.z,b0.w,b1.x,b1.y,b1.z,b1.w};
            #pragma unroll
            for (int i=0;i<8;i++)
                #pragma unroll
                for (int j=0;j<8;j++) acc[i][j] += ar_[i]*br_[j];
        }
        if (more) {
            As[buf^1][aCol+0][aRow]=an.x; As[buf^1][aCol+1][aRow]=an.y;
            As[buf^1][aCol+2][aRow]=an.z; As[buf^1][aCol+3][aRow]=an.w;
            *(float4*)&Bs[buf^1][bRow][bCol] = bn;
            __syncthreads();
            buf ^= 1;
        }
    }
    #pragma unroll
    for (int i=0;i<8;i++){
        int r = row0 + trow*8 + i;
        if (r < M) {
            *(float4*)&C[(size_t)r*128 + tcol*8]   = make_float4(acc[i][0],acc[i][1],acc[i][2],acc[i][3]);
            *(float4*)&C[(size_t)r*128 + tcol*8+4] = make_float4(acc[i][4],acc[i][5],acc[i][6],acc[i][7]);
        }
    }
}

// ---------------- edgedot body: per-edge attention dots + deg + esum -----------
__device__ __forceinline__ void edgedot_body(const float* __restrict__ ef,
                                             const int* __restrict__ dst, int eb) {
    __shared__ float w1[EDIM], w2[EDIM];
    int t = threadIdx.x;
    if (t < EDIM) { w1[t]=d_wvec1[t]; w2[t]=d_wvec2[t]; }
    __syncthreads();
    int e    = eb*8 + (t>>5);
    int lane = t & 31;
    if (e >= NE) return;
    const float* row = ef + (size_t)e*EDIM;
    float x0 = row[lane];
    float v1 = x0*w1[lane], v2 = x0*w2[lane];
    if (lane < EDIM-32) {
        float x1 = row[lane+32];
        v1 += x1*w1[lane+32]; v2 += x1*w2[lane+32];
    }
    #pragma unroll
    for (int o=16;o;o>>=1){ v1 += __shfl_down_sync(~0u,v1,o); v2 += __shfl_down_sync(~0u,v2,o); }
    if (lane==0){
        d_aE1[e]=v1; d_aE2[e]=v2;
        int dd = dst[e];
        atomicAdd(&d_esum1[dd], v1);
        atomicAdd(&d_esum2[dd], v2);
        atomicAdd(&d_deg[dd], 1);
    }
}

// ---------------- K_A: sgemm1 (long pole) fused with edgedot -------------------
__global__ void __launch_bounds__(256,2) k_A(const float* __restrict__ x,
                                             const float* __restrict__ W1,
                                             float* __restrict__ h,
                                             const float* __restrict__ ef,
                                             const int* __restrict__ dst) {
    if (blockIdx.x < G1BLK) sgemm_body(x, W1, h, NN, FIN, blockIdx.x);
    else                    edgedot_body(ef, dst, blockIdx.x - G1BLK);
}

// ---------------- scan of deg, 2-level ----------------
__global__ void k_scan1() {
    __shared__ int sm[1024];
    int b = blockIdx.x, t = threadIdx.x, i = b*1024 + t;
    int v = (i < NN) ? d_deg[i] : 0;
    sm[t]=v; __syncthreads();
    for (int o=1;o<1024;o<<=1){
        int ad = (t>=o) ? sm[t-o] : 0;
        __syncthreads(); sm[t]+=ad; __syncthreads();
    }
    if (i < NN) d_rows[i] = sm[t];
    if (t == 1023) d_bsum[b] = sm[1023];
}

// ---------------- per-node attention scalars ----------------
__device__ __forceinline__ void alpha_body(const float* __restrict__ h,
                                           const float* __restrict__ asrc,
                                           const float* __restrict__ adst, int node) {
    int lane = threadIdx.x & 31;
    if (node >= NN) return;
    const float* row = h + (size_t)node*HD;
    float s=0.f, d=0.f;
    #pragma unroll
    for (int q=0;q<4;q++){
        float v = row[lane+32*q];
        s += v*asrc[lane+32*q];
        d += v*adst[lane+32*q];
    }
    #pragma unroll
    for (int o=16;o;o>>=1){ s += __shfl_xor_sync(~0u,s,o); d += __shfl_xor_sync(~0u,d,o); }
    if (lane==0){ d_as[node]=s; d_ad[node]=d; }
}

// K_C: block0 = block-offset scan, rest = alpha layer1
__global__ void k_C(const float* __restrict__ h,
                    const float* __restrict__ asrc, const float* __restrict__ adst) {
    if (blockIdx.x == 0) {
        if (threadIdx.x == 0) {
            int run = 0;
            for (int b=0;b<SCANB;b++){ d_boff[b]=run; run += d_bsum[b]; }
        }
        return;
    }
    int node = (blockIdx.x-1)*8 + (threadIdx.x>>5);
    alpha_body(h, asrc, adst, node);
}

__global__ void k_alpha(const float* __restrict__ h,
                        const float* __restrict__ asrc, const float* __restrict__ adst) {
    alpha_body(h, asrc, adst, blockIdx.x*8 + (threadIdx.x>>5));
}

__global__ void k_scatter(const int* __restrict__ dst) {
    int e = blockIdx.x*blockDim.x + threadIdx.x;
    if (e < NE) {
        int d = dst[e];
        d_csr[startOf(d) + atomicAdd(&d_cursor[d], 1)] = e;
    }
}

// ---------------- aggregate: warp per node, float4 channels --------------------
__global__ void __launch_bounds__(256) k_aggregate(
        const float* __restrict__ h, const float* __restrict__ aE,
        const float* __restrict__ esum, const int* __restrict__ srcArr,
        const float* __restrict__ bias, float* __restrict__ out, int doRelu) {
    int node = blockIdx.x*8 + (threadIdx.x>>5);
    int lane = threadIdx.x & 31;
    if (node >= NN) return;
    int r0   = startOf(node);
    int degi = d_deg[node];
    float adi   = d_ad[node];
    float aself = lrelu(d_as[node] + adi + esum[node]/fmaxf((float)degi,1.f));

    // pass 1: max
    float m = aself;
    for (int j=lane; j<degi; j+=32) {
        int e = d_csr[r0+j];
        m = fmaxf(m, lrelu(d_as[srcArr[e]] + adi + aE[e]));
    }
    #pragma unroll
    for (int o=16;o;o>>=1) m = fmaxf(m, __shfl_xor_sync(~0u,m,o));

    // pass 2: exp-weighted accumulation
    float4 acc = make_float4(0.f,0.f,0.f,0.f);
    float dsum = 0.f;
    const float4* h4 = (const float4*)h;
    for (int c0=0; c0<degi; c0+=32) {
        int j = c0 + lane;
        float coef = 0.f; int s = 0;
        if (j < degi) {
            int e = d_csr[r0+j];
            s = srcArr[e];
            coef = __expf(lrelu(d_as[s] + adi + aE[e]) - m);
        }
        dsum += coef;
        int cnt = min(32, degi - c0);
        for (int q=0;q<cnt;q++){
            float c  = __shfl_sync(~0u, coef, q);
            int   ss = __shfl_sync(~0u, s,    q);
            float4 hv = h4[(size_t)ss*32 + lane];
            acc.x += c*hv.x; acc.y += c*hv.y; acc.z += c*hv.z; acc.w += c*hv.w;
        }
    }
    #pragma unroll
    for (int o=16;o;o>>=1) dsum += __shfl_xor_sync(~0u,dsum,o);

    float eself = __expf(aself - m);
    dsum += eself;
    float4 hv = h4[(size_t)node*32 + lane];
    acc.x += eself*hv.x; acc.y += eself*hv.y; acc.z += eself*hv.z; acc.w += eself*hv.w;
    float inv = 1.f/dsum;
    float4 b4 = ((const float4*)bias)[lane];
    float4 o4 = make_float4(acc.x*inv + b4.x, acc.y*inv + b4.y,
                            acc.z*inv + b4.z, acc.w*inv + b4.w);
    if (doRelu) {
        o4.x = fmaxf(o4.x,0.f); o4.y = fmaxf(o4.y,0.f);
        o4.z = fmaxf(o4.z,0.f); o4.w = fmaxf(o4.w,0.f);
    }
    ((float4*)out)[(size_t)node*32 + lane] = o4;
}

__global__ void __launch_bounds__(256,2) k_gemm2(const float* __restrict__ A,
                                                 const float* __restrict__ B,
                                                 float* __restrict__ C) {
    sgemm_body(A, B, C, NN, HD, blockIdx.x);
}

// ---------------- decode: warp per output pair, float4 ----------------
__global__ void k_decode(const int* __restrict__ srcArr, const int* __restrict__ dstArr,
                         float* __restrict__ out) {
    int w    = blockIdx.x*8 + (threadIdx.x>>5);
    int lane = threadIdx.x & 31;
    if (w >= NE/2) return;
    const float4* z4 = (const float4*)d_z;
    float4 a1 = z4[(size_t)srcArr[w]*32 + lane];
    float4 b1 = z4[(size_t)dstArr[w]*32 + lane];
    float4 a2 = z4[(size_t)srcArr[w+NE/2]*32 + lane];
    float4 b2 = z4[(size_t)dstArr[w+NE/2]*32 + lane];
    float s = a1.x*b1.x + a1.y*b1.y + a1.z*b1.z + a1.w*b1.w
            + a2.x*b2.x + a2.y*b2.y + a2.z*b2.z + a2.w*b2.w;
    #pragma unroll
    for (int o=16;o;o>>=1) s += __shfl_down_sync(~0u,s,o);
    if (lane==0) out[w] = s;
}

// ---------------- launch ----------------
extern "C" void kernel_launch(void* const* d_in, const int* in_sizes, int n_in,
                              void* d_out, int out_size) {
    const float* x    = (const float*)d_in[0];
    const int*   ei   = (const int*)  d_in[1];
    const float* ef   = (const float*)d_in[2];
    const float* W1   = (const float*)d_in[4];
    const float* as1  = (const float*)d_in[5];
    const float* ad1  = (const float*)d_in[6];
    const float* We1  = (const float*)d_in[7];
    const float* ae1  = (const float*)d_in[8];
    const float* b1   = (const float*)d_in[9];
    const float* W2   = (const float*)d_in[10];
    const float* as2  = (const float*)d_in[11];
    const float* ad2  = (const float*)d_in[12];
    const float* We2  = (const float*)d_in[13];
    const float* ae2  = (const float*)d_in[14];
    const float* b2   = (const float*)d_in[15];
    const int* src = ei;
    const int* dst = ei + NE;

    float* h;   cudaGetSymbolAddress((void**)&h,   d_h);
    float* g;   cudaGetSymbolAddress((void**)&g,   d_g);
    float* z;   cudaGetSymbolAddress((void**)&z,   d_z);
    float* aE1; cudaGetSymbolAddress((void**)&aE1, d_aE1);
    float* aE2; cudaGetSymbolAddress((void**)&aE2, d_aE2);
    float* es1; cudaGetSymbolAddress((void**)&es1, d_esum1);
    float* es2; cudaGetSymbolAddress((void**)&es2, d_esum2);

    k_pre<<<(NN+255)/256, 256>>>(We1, ae1, We2, ae2);
    k_A<<<G1BLK + EDBLK, 256>>>(x, W1, h, ef, dst);      // sgemm1 || edgedot
    k_scan1<<<SCANB, 1024>>>();
    k_C<<<1 + ALPHABLK, 256>>>(h, as1, ad1);             // boff scan || alpha1
    k_scatter<<<(NE+255)/256, 256>>>(dst);
    k_aggregate<<<(NN+7)/8, 256>>>(h, aE1, es1, src, b1, g, 1);

    k_gemm2<<<G1BLK, 256>>>(g, W2, h);
    k_alpha<<<ALPHABLK, 256>>>(h, as2, ad2);
    k_aggregate<<<(NN+7)/8, 256>>>(h, aE2, es2, src, b2, z, 0);

    k_decode<<<(NE/2+7)/8, 256>>>(src, dst, (float*)d_out);
}

// round 4
// speedup vs baseline: 1.3721x; 1.3721x over previous
#include <cuda_runtime.h>
#include <math.h>

#define NN   50000
#define NE   800000
#define FIN  256
#define HD   128
#define EDIM 60
#define NEG_SLOPE 0.2f
#define SCANB 49                 // ceil(NN/1024)

// ---------------- scratch ----------------
__device__ float d_h [NN*HD];
__device__ float d_g [NN*HD];
__device__ float d_z [NN*HD];
__device__ float d_as[NN], d_ad[NN];
__device__ float d_aE1[NE], d_aE2[NE];
__device__ float d_esum1[NN], d_esum2[NN];
__device__ int   d_deg[NN];
__device__ int   d_rows[NN];      // inclusive scan of deg within each 1024-block
__device__ int   d_bsum[SCANB];
__device__ int   d_boff[SCANB];   // exclusive scan of bsum
__device__ int   d_scandone = 0;
__device__ int   d_cursor[NN];
__device__ int   d_csr[NE];
__device__ float d_wvec1[EDIM], d_wvec2[EDIM];

__device__ __forceinline__ float lrelu(float v){ return v > 0.f ? v : NEG_SLOPE*v; }
__device__ __forceinline__ int startOf(int d){
    return (d == 0) ? 0 : d_rows[d-1] + d_boff[(d-1)>>10];
}

// ---------------- k_pre: zero accumulators + wvec = We @ a_edge ----------------
__global__ void k_pre(const float* __restrict__ We1, const float* __restrict__ ae1,
                      const float* __restrict__ We2, const float* __restrict__ ae2) {
    int i = blockIdx.x*blockDim.x + threadIdx.x;
    if (i < NN) { d_deg[i]=0; d_esum1[i]=0.f; d_esum2[i]=0.f; d_cursor[i]=0; }
    if (blockIdx.x == 0 && threadIdx.x < EDIM) {
        int j = threadIdx.x;
        float s1=0.f, s2=0.f;
        for (int c=0;c<HD;c++){ s1 += We1[j*HD+c]*ae1[c]; s2 += We2[j*HD+c]*ae2[c]; }
        d_wvec1[j]=s1; d_wvec2[j]=s2;
    }
}

// ---------------- edgedot: per-edge attention dots (both layers) + deg + esum --
__global__ void k_edgedot(const float* __restrict__ ef, const int* __restrict__ dst) {
    __shared__ float w1[EDIM], w2[EDIM];
    int t = threadIdx.x;
    if (t < EDIM) { w1[t]=d_wvec1[t]; w2[t]=d_wvec2[t]; }
    __syncthreads();
    int e    = blockIdx.x*8 + (t>>5);
    int lane = t & 31;
    if (e >= NE) return;
    const float* row = ef + (size_t)e*EDIM;
    float x0 = row[lane];
    float v1 = x0*w1[lane], v2 = x0*w2[lane];
    if (lane < EDIM-32) {
        float x1 = row[lane+32];
        v1 += x1*w1[lane+32]; v2 += x1*w2[lane+32];
    }
    #pragma unroll
    for (int o=16;o;o>>=1){ v1 += __shfl_down_sync(~0u,v1,o); v2 += __shfl_down_sync(~0u,v2,o); }
    if (lane==0){
        d_aE1[e]=v1; d_aE2[e]=v2;
        int dd = dst[e];
        atomicAdd(&d_esum1[dd], v1);
        atomicAdd(&d_esum2[dd], v2);
        atomicAdd(&d_deg[dd], 1);
    }
}

// ---------------- scan: 49 blocks + last-block-done finalize -------------------
__global__ void k_scan1() {
    __shared__ int sm[1024];
    __shared__ bool isLast;
    int b = blockIdx.x, t = threadIdx.x, i = b*1024 + t;
    int v = (i < NN) ? d_deg[i] : 0;
    sm[t]=v; __syncthreads();
    for (int o=1;o<1024;o<<=1){
        int ad = (t>=o) ? sm[t-o] : 0;
        __syncthreads(); sm[t]+=ad; __syncthreads();
    }
    if (i < NN) d_rows[i] = sm[t];
    if (t == 1023) d_bsum[b] = sm[1023];
    __threadfence();
    if (t == 0) isLast = (atomicAdd(&d_scandone, 1) == SCANB-1);
    __syncthreads();
    if (isLast && t == 0) {
        int run = 0;
        for (int q=0;q<SCANB;q++){ d_boff[q]=run; run += d_bsum[q]; }
        d_scandone = 0;
        __threadfence();
    }
}

__global__ void k_scatter(const int* __restrict__ dst) {
    int e = blockIdx.x*blockDim.x + threadIdx.x;
    if (e < NE) {
        int d = dst[e];
        d_csr[startOf(d) + atomicAdd(&d_cursor[d], 1)] = e;
    }
}

// ---------------- SGEMM: C[M,128]=A[M,K]@B[K,128], fp32, 128x128x8 (R2) --------
__global__ void __launch_bounds__(256) k_sgemm(const float* __restrict__ A,
                                               const float* __restrict__ B,
                                               float* __restrict__ C, int M, int K) {
    constexpr int BM=128, BN=128, BK=8, TM=8, TN=8;
    __shared__ float As[BK][BM];
    __shared__ float Bs[BK][BN];
    int tid  = threadIdx.x;
    int tcol = tid & 15;
    int trow = tid >> 4;
    int row0 = blockIdx.x * BM;
    int aRow = tid >> 1;
    int aCol = (tid & 1) * 4;
    int bRow = tid >> 5;
    int bCol = (tid & 31) * 4;
    float acc[TM][TN];
    #pragma unroll
    for (int i=0;i<TM;i++)
        #pragma unroll
        for (int j=0;j<TN;j++) acc[i][j]=0.f;

    for (int k0=0; k0<K; k0+=BK) {
        int ar = row0 + aRow;
        float4 a4 = make_float4(0.f,0.f,0.f,0.f);
        if (ar < M) a4 = *(const float4*)&A[(size_t)ar*K + k0 + aCol];
        As[aCol+0][aRow]=a4.x; As[aCol+1][aRow]=a4.y;
        As[aCol+2][aRow]=a4.z; As[aCol+3][aRow]=a4.w;
        *(float4*)&Bs[bRow][bCol] = *(const float4*)&B[(size_t)(k0+bRow)*BN + bCol];
        __syncthreads();
        #pragma unroll
        for (int k=0;k<BK;k++){
            float4 a0 = *(const float4*)&As[k][trow*TM];
            float4 a1 = *(const float4*)&As[k][trow*TM+4];
            float4 b0 = *(const float4*)&Bs[k][tcol*TN];
            float4 b1 = *(const float4*)&Bs[k][tcol*TN+4];
            float ar_[TM] = {a0.x,a0.y,a0.z,a0.w,a1.x,a1.y,a1.z,a1.w};
            float br_[TN] = {b0.x,b0.y,b0.z,b0.w,b1.x,b1.y,b1.z,b1.w};
            #pragma unroll
            for (int i=0;i<TM;i++)
                #pragma unroll
                for (int j=0;j<TN;j++) acc[i][j] += ar_[i]*br_[j];
        }
        __syncthreads();
    }
    #pragma unroll
    for (int i=0;i<TM;i++){
        int r = row0 + trow*TM + i;
        if (r < M) {
            *(float4*)&C[(size_t)r*BN + tcol*TN]     = make_float4(acc[i][0],acc[i][1],acc[i][2],acc[i][3]);
            *(float4*)&C[(size_t)r*BN + tcol*TN + 4] = make_float4(acc[i][4],acc[i][5],acc[i][6],acc[i][7]);
        }
    }
}

// ---------------- per-node attention scalars ----------------
__global__ void k_alpha(const float* __restrict__ h,
                        const float* __restrict__ asrc, const float* __restrict__ adst) {
    int node = blockIdx.x*8 + (threadIdx.x>>5);
    int lane = threadIdx.x & 31;
    if (node >= NN) return;
    const float* row = h + (size_t)node*HD;
    float s=0.f, d=0.f;
    #pragma unroll
    for (int q=0;q<4;q++){
        float v = row[lane+32*q];
        s += v*asrc[lane+32*q];
        d += v*adst[lane+32*q];
    }
    #pragma unroll
    for (int o=16;o;o>>=1){ s += __shfl_xor_sync(~0u,s,o); d += __shfl_xor_sync(~0u,d,o); }
    if (lane==0){ d_as[node]=s; d_ad[node]=d; }
}

// ---------------- aggregate: block per node (R2), smem-broadcast coefficients --
__global__ void __launch_bounds__(128) k_aggregate(
        const float* __restrict__ h, const float* __restrict__ aE,
        const float* __restrict__ esum, const int* __restrict__ srcArr,
        const float* __restrict__ bias, float* __restrict__ out, int doRelu) {
    int i = blockIdx.x;
    int t = threadIdx.x;
    __shared__ float sm_e[128];
    __shared__ int   sm_s[128];
    __shared__ float red[128];
    int r0   = startOf(i);
    int degi = d_deg[i];
    float adi = d_ad[i];
    float aself = lrelu(d_as[i] + adi + esum[i]/fmaxf((float)degi, 1.f));
    // phase 1: max
    float m = aself;
    for (int j=t; j<degi; j+=128) {
        int e = d_csr[r0+j];
        m = fmaxf(m, lrelu(d_as[srcArr[e]] + adi + aE[e]));
    }
    red[t]=m; __syncthreads();
    #pragma unroll
    for (int o=64;o;o>>=1){ if (t<o) red[t]=fmaxf(red[t],red[t+o]); __syncthreads(); }
    m = red[0];
    __syncthreads();
    // phase 2: unnormalized accumulation, divide at end
    float acc = 0.f, dsum = 0.f;
    for (int j0=0; j0<degi; j0+=128) {
        int j = j0 + t;
        float ea = 0.f; int s = 0;
        if (j < degi) {
            int e = d_csr[r0+j];
            s = srcArr[e];
            ea = __expf(lrelu(d_as[s] + adi + aE[e]) - m);
        }
        sm_e[t]=ea; sm_s[t]=s;
        __syncthreads();
        int cnt = min(128, degi - j0);
        for (int q=0;q<cnt;q++){
            float c = sm_e[q];
            acc  += c * h[(size_t)sm_s[q]*HD + t];
            dsum += c;
        }
        __syncthreads();
    }
    float eself = __expf(aself - m);
    dsum += eself;
    acc  += eself * h[(size_t)i*HD + t];
    float o = acc/dsum + bias[t];
    if (doRelu) o = fmaxf(o, 0.f);
    out[(size_t)i*HD + t] = o;
}

// ---------------- decode: warp per output pair, float4 ----------------
__global__ void k_decode(const int* __restrict__ srcArr, const int* __restrict__ dstArr,
                         float* __restrict__ out) {
    int w    = blockIdx.x*8 + (threadIdx.x>>5);
    int lane = threadIdx.x & 31;
    if (w >= NE/2) return;
    const float4* z4 = (const float4*)d_z;
    float4 a1 = z4[(size_t)srcArr[w]*32 + lane];
    float4 b1 = z4[(size_t)dstArr[w]*32 + lane];
    float4 a2 = z4[(size_t)srcArr[w+NE/2]*32 + lane];
    float4 b2 = z4[(size_t)dstArr[w+NE/2]*32 + lane];
    float s = a1.x*b1.x + a1.y*b1.y + a1.z*b1.z + a1.w*b1.w
            + a2.x*b2.x + a2.y*b2.y + a2.z*b2.z + a2.w*b2.w;
    #pragma unroll
    for (int o=16;o;o>>=1) s += __shfl_down_sync(~0u,s,o);
    if (lane==0) out[w] = s;
}

// ---------------- launch ----------------
extern "C" void kernel_launch(void* const* d_in, const int* in_sizes, int n_in,
                              void* d_out, int out_size) {
    const float* x    = (const float*)d_in[0];
    const int*   ei   = (const int*)  d_in[1];
    const float* ef   = (const float*)d_in[2];
    const float* W1   = (const float*)d_in[4];
    const float* as1  = (const float*)d_in[5];
    const float* ad1  = (const float*)d_in[6];
    const float* We1  = (const float*)d_in[7];
    const float* ae1  = (const float*)d_in[8];
    const float* b1   = (const float*)d_in[9];
    const float* W2   = (const float*)d_in[10];
    const float* as2  = (const float*)d_in[11];
    const float* ad2  = (const float*)d_in[12];
    const float* We2  = (const float*)d_in[13];
    const float* ae2  = (const float*)d_in[14];
    const float* b2   = (const float*)d_in[15];
    const int* src = ei;
    const int* dst = ei + NE;

    float* h;   cudaGetSymbolAddress((void**)&h,   d_h);
    float* g;   cudaGetSymbolAddress((void**)&g,   d_g);
    float* z;   cudaGetSymbolAddress((void**)&z,   d_z);
    float* aE1; cudaGetSymbolAddress((void**)&aE1, d_aE1);
    float* aE2; cudaGetSymbolAddress((void**)&aE2, d_aE2);
    float* es1; cudaGetSymbolAddress((void**)&es1, d_esum1);
    float* es2; cudaGetSymbolAddress((void**)&es2, d_esum2);

    k_pre<<<(NN+255)/256, 256>>>(We1, ae1, We2, ae2);
    k_edgedot<<<NE/8, 256>>>(ef, dst);
    k_scan1<<<SCANB, 1024>>>();
    k_scatter<<<(NE+255)/256, 256>>>(dst);

    // layer 1
    k_sgemm<<<(NN+127)/128, 256>>>(x, W1, h, NN, FIN);
    k_alpha<<<(NN+7)/8, 256>>>(h, as1, ad1);
    k_aggregate<<<NN, 128>>>(h, aE1, es1, src, b1, g, 1);

    // layer 2
    k_sgemm<<<(NN+127)/128, 256>>>(g, W2, h, NN, HD);
    k_alpha<<<(NN+7)/8, 256>>>(h, as2, ad2);
    k_aggregate<<<NN, 128>>>(h, aE2, es2, src, b2, z, 0);

    // decode
    k_decode<<<(NE/2+7)/8, 256>>>(src, dst, (float*)d_out);
}

// round 9
// speedup vs baseline: 1.5521x; 1.1312x over previous
#include <cuda_runtime.h>
#include <cuda_bf16.h>
#include <math.h>
#include <stdint.h>

#define NN   50000
#define NE   800000
#define FIN  256
#define HD   128
#define EDIM 60
#define NEG_SLOPE 0.2f
#define SCANB 49
#define GTILES ((NN+127)/128)    // 391
#define ST 40                    // smem row stride (bf16 elems) to dodge bank conflicts

// ================= scratch =================
__device__ float d_h [NN*HD];
__device__ float d_z [NN*HD];
__device__ __nv_bfloat16 d_xh[NN*FIN], d_xl[NN*FIN];
__device__ __nv_bfloat16 d_gh[NN*HD],  d_gl[NN*HD];
__device__ __nv_bfloat16 d_wt1h[HD*FIN], d_wt1l[HD*FIN];   // [n][k] transposed W1
__device__ __nv_bfloat16 d_wt2h[HD*HD],  d_wt2l[HD*HD];
__device__ float d_as[NN], d_ad[NN];
__device__ float d_aE1[NE], d_aE2[NE];
__device__ float d_esum1[NN], d_esum2[NN];
__device__ int   d_deg[NN];
__device__ int   d_rows[NN];
__device__ int   d_bsum[SCANB];
__device__ int   d_boff[SCANB];
__device__ int   d_scandone = 0;
__device__ int   d_cursor[NN];
__device__ int   d_csr[NE];
__device__ float d_wvec1[EDIM], d_wvec2[EDIM];

__device__ __forceinline__ float lrelu(float v){ return v > 0.f ? v : NEG_SLOPE*v; }
__device__ __forceinline__ int startOf(int d){
    return (d == 0) ? 0 : d_rows[d-1] + d_boff[(d-1)>>10];
}

// ================= setup kernels =================
__global__ void k_pre(const float* __restrict__ We1, const float* __restrict__ ae1,
                      const float* __restrict__ We2, const float* __restrict__ ae2) {
    int i = blockIdx.x*blockDim.x + threadIdx.x;
    if (i < NN) { d_deg[i]=0; d_esum1[i]=0.f; d_esum2[i]=0.f; d_cursor[i]=0; }
    if (blockIdx.x == 0 && threadIdx.x < EDIM) {
        int j = threadIdx.x;
        float s1=0.f, s2=0.f;
        for (int c=0;c<HD;c++){ s1 += We1[j*HD+c]*ae1[c]; s2 += We2[j*HD+c]*ae2[c]; }
        d_wvec1[j]=s1; d_wvec2[j]=s2;
    }
}

// split x into bf16 hi/lo
__global__ void k_splitX(const float* __restrict__ x) {
    int i = blockIdx.x*blockDim.x + threadIdx.x;       // float4 index
    if (i*4 >= NN*FIN) return;
    float4 v = ((const float4*)x)[i];
    __nv_bfloat16 h0=__float2bfloat16(v.x), h1=__float2bfloat16(v.y),
                  h2=__float2bfloat16(v.z), h3=__float2bfloat16(v.w);
    __nv_bfloat16 l0=__float2bfloat16(v.x-__bfloat162float(h0)),
                  l1=__float2bfloat16(v.y-__bfloat162float(h1)),
                  l2=__float2bfloat16(v.z-__bfloat162float(h2)),
                  l3=__float2bfloat16(v.w-__bfloat162float(h3));
    __nv_bfloat162* xh2 = (__nv_bfloat162*)d_xh;
    __nv_bfloat162* xl2 = (__nv_bfloat162*)d_xl;
    xh2[i*2]   = __nv_bfloat162(h0,h1); xh2[i*2+1] = __nv_bfloat162(h2,h3);
    xl2[i*2]   = __nv_bfloat162(l0,l1); xl2[i*2+1] = __nv_bfloat162(l2,l3);
}

// transpose + split W1 (256x128) and W2 (128x128) into [n][k] bf16 hi/lo
__global__ void k_prepW(const float* __restrict__ W1, const float* __restrict__ W2) {
    int i = blockIdx.x*blockDim.x + threadIdx.x;
    if (i < FIN*HD) {
        int k = i >> 7, n = i & 127;
        float v = W1[i];
        __nv_bfloat16 hh = __float2bfloat16(v);
        d_wt1h[n*FIN+k] = hh;
        d_wt1l[n*FIN+k] = __float2bfloat16(v - __bfloat162float(hh));
    } else if (i < FIN*HD + HD*HD) {
        int j = i - FIN*HD;
        int k = j >> 7, n = j & 127;
        float v = W2[j];
        __nv_bfloat16 hh = __float2bfloat16(v);
        d_wt2h[n*HD+k] = hh;
        d_wt2l[n*HD+k] = __float2bfloat16(v - __bfloat162float(hh));
    }
}

// ================= edge pipeline (unchanged from R4) =================
__global__ void k_edgedot(const float* __restrict__ ef, const int* __restrict__ dst) {
    __shared__ float w1[EDIM], w2[EDIM];
    int t = threadIdx.x;
    if (t < EDIM) { w1[t]=d_wvec1[t]; w2[t]=d_wvec2[t]; }
    __syncthreads();
    int e    = blockIdx.x*8 + (t>>5);
    int lane = t & 31;
    if (e >= NE) return;
    const float* row = ef + (size_t)e*EDIM;
    float x0 = row[lane];
    float v1 = x0*w1[lane], v2 = x0*w2[lane];
    if (lane < EDIM-32) {
        float x1 = row[lane+32];
        v1 += x1*w1[lane+32]; v2 += x1*w2[lane+32];
    }
    #pragma unroll
    for (int o=16;o;o>>=1){ v1 += __shfl_down_sync(~0u,v1,o); v2 += __shfl_down_sync(~0u,v2,o); }
    if (lane==0){
        d_aE1[e]=v1; d_aE2[e]=v2;
        int dd = dst[e];
        atomicAdd(&d_esum1[dd], v1);
        atomicAdd(&d_esum2[dd], v2);
        atomicAdd(&d_deg[dd], 1);
    }
}

__global__ void k_scan1() {
    __shared__ int sm[1024];
    __shared__ bool isLast;
    int b = blockIdx.x, t = threadIdx.x, i = b*1024 + t;
    int v = (i < NN) ? d_deg[i] : 0;
    sm[t]=v; __syncthreads();
    for (int o=1;o<1024;o<<=1){
        int ad = (t>=o) ? sm[t-o] : 0;
        __syncthreads(); sm[t]+=ad; __syncthreads();
    }
    if (i < NN) d_rows[i] = sm[t];
    if (t == 1023) d_bsum[b] = sm[1023];
    __threadfence();
    if (t == 0) isLast = (atomicAdd(&d_scandone, 1) == SCANB-1);
    __syncthreads();
    if (isLast && t == 0) {
        int run = 0;
        for (int q=0;q<SCANB;q++){ d_boff[q]=run; run += d_bsum[q]; }
        d_scandone = 0;
        __threadfence();
    }
}

__global__ void k_scatter(const int* __restrict__ dst) {
    int e = blockIdx.x*blockDim.x + threadIdx.x;
    if (e < NE) {
        int d = dst[e];
        d_csr[startOf(d) + atomicAdd(&d_cursor[d], 1)] = e;
    }
}

// ================= mma.sync bf16x3 GEMM ======================================
// C[M,128] = (Ah+Al) @ (Bh+Bl)^T, fp32 accum.
// A: [M,KT] row-major bf16 hi/lo. B: [128,KT] bf16 hi/lo (pre-transposed weight,
// which is exactly col-major for mma.sync row.col).
// Block: 256 thr, 128x128 tile; warp (wm=wid>>1, wn=wid&1) -> 32x64 subtile;
// per-warp: 2 m-frags x 8 n-frags of m16n8k16, 3 MMAs per frag (hi*hi, lo*hi, hi*lo).
__device__ __forceinline__ void mma16816(float c[4], const uint32_t a[4], const uint32_t b[2]) {
    asm volatile("mma.sync.aligned.m16n8k16.row.col.f32.bf16.bf16.f32 "
        "{%0,%1,%2,%3}, {%4,%5,%6,%7}, {%8,%9}, {%0,%1,%2,%3};"
        : "+f"(c[0]), "+f"(c[1]), "+f"(c[2]), "+f"(c[3])
        : "r"(a[0]), "r"(a[1]), "r"(a[2]), "r"(a[3]), "r"(b[0]), "r"(b[1]));
}

__global__ void __launch_bounds__(256) k_hgemm(
        const __nv_bfloat16* __restrict__ Ah, const __nv_bfloat16* __restrict__ Al,
        const __nv_bfloat16* __restrict__ Bh, const __nv_bfloat16* __restrict__ Bl,
        float* __restrict__ C, int M, int KT) {
    __shared__ __nv_bfloat16 sAh[128*ST], sAl[128*ST];
    __shared__ __nv_bfloat16 sBh[128*ST], sBl[128*ST];
    int tid  = threadIdx.x;
    int wid  = tid >> 5, lane = tid & 31;
    int wm   = wid >> 1, wn = wid & 1;
    int r    = lane >> 2, t = lane & 3;
    int row0 = blockIdx.x * 128;

    float acc[2][8][4];
    #pragma unroll
    for (int mi=0;mi<2;mi++)
        #pragma unroll
        for (int ni=0;ni<8;ni++)
            #pragma unroll
            for (int q=0;q<4;q++) acc[mi][ni][q]=0.f;

    for (int k0 = 0; k0 < KT; k0 += 32) {
        // stage 128x32 of each matrix: 512 uint4 per matrix, 2 per thread
        #pragma unroll
        for (int it = 0; it < 2; it++) {
            int q   = tid + it*256;
            int row = q >> 2, cb = q & 3;
            int so  = row*ST + cb*8;
            size_t ao = (size_t)(row0+row)*KT + k0 + cb*8;
            uint4 vh = make_uint4(0,0,0,0), vl = vh;
            if (row0 + row < M) {
                vh = *(const uint4*)(Ah + ao);
                vl = *(const uint4*)(Al + ao);
            }
            *(uint4*)&sAh[so] = vh;
            *(uint4*)&sAl[so] = vl;
            size_t bo = (size_t)row*KT + k0 + cb*8;
            *(uint4*)&sBh[so] = *(const uint4*)(Bh + bo);
            *(uint4*)&sBl[so] = *(const uint4*)(Bl + bo);
        }
        __syncthreads();
        #pragma unroll
        for (int ks = 0; ks < 2; ks++) {
            int kb = ks*16 + 2*t;
            uint32_t ah[2][4], al[2][4], bh[8][2], bl[8][2];
            #pragma unroll
            for (int mi=0;mi<2;mi++){
                int rb = wm*32 + mi*16 + r;
                ah[mi][0] = *(const uint32_t*)&sAh[ rb    *ST + kb    ];
                ah[mi][1] = *(const uint32_t*)&sAh[(rb+8) *ST + kb    ];
                ah[mi][2] = *(const uint32_t*)&sAh[ rb    *ST + kb + 8];
                ah[mi][3] = *(const uint32_t*)&sAh[(rb+8) *ST + kb + 8];
                al[mi][0] = *(const uint32_t*)&sAl[ rb    *ST + kb    ];
                al[mi][1] = *(const uint32_t*)&sAl[(rb+8) *ST + kb    ];
                al[mi][2] = *(const uint32_t*)&sAl[ rb    *ST + kb + 8];
                al[mi][3] = *(const uint32_t*)&sAl[(rb+8) *ST + kb + 8];
            }
            #pragma unroll
            for (int ni=0;ni<8;ni++){
                int nb = wn*64 + ni*8 + r;
                bh[ni][0] = *(const uint32_t*)&sBh[nb*ST + kb    ];
                bh[ni][1] = *(const uint32_t*)&sBh[nb*ST + kb + 8];
                bl[ni][0] = *(const uint32_t*)&sBl[nb*ST + kb    ];
                bl[ni][1] = *(const uint32_t*)&sBl[nb*ST + kb + 8];
            }
            #pragma unroll
            for (int mi=0;mi<2;mi++)
                #pragma unroll
                for (int ni=0;ni<8;ni++){
                    mma16816(acc[mi][ni], ah[mi], bh[ni]);
                    mma16816(acc[mi][ni], al[mi], bh[ni]);
                    mma16816(acc[mi][ni], ah[mi], bl[ni]);
                }
        }
        __syncthreads();
    }
    // epilogue: c0,c1 -> (row, 2t/2t+1); c2,c3 -> (row+8, ...)
    #pragma unroll
    for (int mi=0;mi<2;mi++){
        int gr = row0 + wm*32 + mi*16 + r;
        #pragma unroll
        for (int ni=0;ni<8;ni++){
            int gc = wn*64 + ni*8 + 2*t;
            if (gr < M)
                *(float2*)&C[(size_t)gr*128 + gc]    = make_float2(acc[mi][ni][0], acc[mi][ni][1]);
            if (gr + 8 < M)
                *(float2*)&C[(size_t)(gr+8)*128 + gc] = make_float2(acc[mi][ni][2], acc[mi][ni][3]);
        }
    }
}

// ================= per-node attention scalars =================
__global__ void k_alpha(const float* __restrict__ h,
                        const float* __restrict__ asrc, const float* __restrict__ adst) {
    int node = blockIdx.x*8 + (threadIdx.x>>5);
    int lane = threadIdx.x & 31;
    if (node >= NN) return;
    const float* row = h + (size_t)node*HD;
    float s=0.f, d=0.f;
    #pragma unroll
    for (int q=0;q<4;q++){
        float v = row[lane+32*q];
        s += v*asrc[lane+32*q];
        d += v*adst[lane+32*q];
    }
    #pragma unroll
    for (int o=16;o;o>>=1){ s += __shfl_xor_sync(~0u,s,o); d += __shfl_xor_sync(~0u,d,o); }
    if (lane==0){ d_as[node]=s; d_ad[node]=d; }
}

// ================= aggregate (block-per-node; split-bf16 output for L1) =======
__global__ void __launch_bounds__(128) k_aggregate(
        const float* __restrict__ h, const float* __restrict__ aE,
        const float* __restrict__ esum, const int* __restrict__ srcArr,
        const float* __restrict__ bias, float* __restrict__ outF,
        __nv_bfloat16* __restrict__ outH, __nv_bfloat16* __restrict__ outL,
        int reluSplit) {
    int i = blockIdx.x;
    int t = threadIdx.x;
    __shared__ float sm_e[128];
    __shared__ int   sm_s[128];
    __shared__ float red[128];
    int r0   = startOf(i);
    int degi = d_deg[i];
    float adi = d_ad[i];
    float aself = lrelu(d_as[i] + adi + esum[i]/fmaxf((float)degi, 1.f));
    float m = aself;
    for (int j=t; j<degi; j+=128) {
        int e = d_csr[r0+j];
        m = fmaxf(m, lrelu(d_as[srcArr[e]] + adi + aE[e]));
    }
    red[t]=m; __syncthreads();
    #pragma unroll
    for (int o=64;o;o>>=1){ if (t<o) red[t]=fmaxf(red[t],red[t+o]); __syncthreads(); }
    m = red[0];
    __syncthreads();
    float acc = 0.f, dsum = 0.f;
    for (int j0=0; j0<degi; j0+=128) {
        int j = j0 + t;
        float ea = 0.f; int s = 0;
        if (j < degi) {
            int e = d_csr[r0+j];
            s = srcArr[e];
            ea = __expf(lrelu(d_as[s] + adi + aE[e]) - m);
        }
        sm_e[t]=ea; sm_s[t]=s;
        __syncthreads();
        int cnt = min(128, degi - j0);
        for (int q=0;q<cnt;q++){
            float c = sm_e[q];
            acc  += c * h[(size_t)sm_s[q]*HD + t];
            dsum += c;
        }
        __syncthreads();
    }
    float eself = __expf(aself - m);
    dsum += eself;
    acc  += eself * h[(size_t)i*HD + t];
    float o = acc/dsum + bias[t];
    size_t idx = (size_t)i*HD + t;
    if (reluSplit) {
        o = fmaxf(o, 0.f);
        __nv_bfloat16 hh = __float2bfloat16(o);
        outH[idx] = hh;
        outL[idx] = __float2bfloat16(o - __bfloat162float(hh));
    } else {
        outF[idx] = o;
    }
}

// ================= decode =================
__global__ void k_decode(const int* __restrict__ srcArr, const int* __restrict__ dstArr,
                         float* __restrict__ out) {
    int w    = blockIdx.x*8 + (threadIdx.x>>5);
    int lane = threadIdx.x & 31;
    if (w >= NE/2) return;
    const float4* z4 = (const float4*)d_z;
    float4 a1 = z4[(size_t)srcArr[w]*32 + lane];
    float4 b1 = z4[(size_t)dstArr[w]*32 + lane];
    float4 a2 = z4[(size_t)srcArr[w+NE/2]*32 + lane];
    float4 b2 = z4[(size_t)dstArr[w+NE/2]*32 + lane];
    float s = a1.x*b1.x + a1.y*b1.y + a1.z*b1.z + a1.w*b1.w
            + a2.x*b2.x + a2.y*b2.y + a2.z*b2.z + a2.w*b2.w;
    #pragma unroll
    for (int o=16;o;o>>=1) s += __shfl_down_sync(~0u,s,o);
    if (lane==0) out[w] = s;
}

// ================= launch =================
extern "C" void kernel_launch(void* const* d_in, const int* in_sizes, int n_in,
                              void* d_out, int out_size) {
    const float* x    = (const float*)d_in[0];
    const int*   ei   = (const int*)  d_in[1];
    const float* ef   = (const float*)d_in[2];
    const float* W1   = (const float*)d_in[4];
    const float* as1  = (const float*)d_in[5];
    const float* ad1  = (const float*)d_in[6];
    const float* We1  = (const float*)d_in[7];
    const float* ae1  = (const float*)d_in[8];
    const float* b1   = (const float*)d_in[9];
    const float* W2   = (const float*)d_in[10];
    const float* as2  = (const float*)d_in[11];
    const float* ad2  = (const float*)d_in[12];
    const float* We2  = (const float*)d_in[13];
    const float* ae2  = (const float*)d_in[14];
    const float* b2   = (const float*)d_in[15];
    const int* src = ei;
    const int* dst = ei + NE;

    float* h;   cudaGetSymbolAddress((void**)&h,   d_h);
    float* z;   cudaGetSymbolAddress((void**)&z,   d_z);
    float* aE1; cudaGetSymbolAddress((void**)&aE1, d_aE1);
    float* aE2; cudaGetSymbolAddress((void**)&aE2, d_aE2);
    float* es1; cudaGetSymbolAddress((void**)&es1, d_esum1);
    float* es2; cudaGetSymbolAddress((void**)&es2, d_esum2);
    __nv_bfloat16 *xh, *xl, *gh, *gl, *wt1h, *wt1l, *wt2h, *wt2l;
    cudaGetSymbolAddress((void**)&xh,  d_xh);
    cudaGetSymbolAddress((void**)&xl,  d_xl);
    cudaGetSymbolAddress((void**)&gh,  d_gh);
    cudaGetSymbolAddress((void**)&gl,  d_gl);
    cudaGetSymbolAddress((void**)&wt1h, d_wt1h);
    cudaGetSymbolAddress((void**)&wt1l, d_wt1l);
    cudaGetSymbolAddress((void**)&wt2h, d_wt2h);
    cudaGetSymbolAddress((void**)&wt2l, d_wt2l);

    k_pre<<<(NN+255)/256, 256>>>(We1, ae1, We2, ae2);
    k_splitX<<<(NN*FIN/4+255)/256, 256>>>(x);
    k_prepW<<<(FIN*HD + HD*HD + 255)/256, 256>>>(W1, W2);
    k_edgedot<<<NE/8, 256>>>(ef, dst);
    k_scan1<<<SCANB, 1024>>>();
    k_scatter<<<(NE+255)/256, 256>>>(dst);

    // layer 1
    k_hgemm<<<GTILES, 256>>>(xh, xl, wt1h, wt1l, h, NN, FIN);
    k_alpha<<<(NN+7)/8, 256>>>(h, as1, ad1);
    k_aggregate<<<NN, 128>>>(h, aE1, es1, src, b1, nullptr, gh, gl, 1);

    // layer 2
    k_hgemm<<<GTILES, 256>>>(gh, gl, wt2h, wt2l, h, NN, HD);
    k_alpha<<<(NN+7)/8, 256>>>(h, as2, ad2);
    k_aggregate<<<NN, 128>>>(h, aE2, es2, src, b2, z, nullptr, nullptr, 0);

    // decode
    k_decode<<<(NE/2+7)/8, 256>>>(src, dst, (float*)d_out);
}

// round 10
// speedup vs baseline: 1.7364x; 1.1188x over previous
#include <cuda_runtime.h>
#include <cuda_bf16.h>
#include <math.h>
#include <stdint.h>

#define NN   50000
#define NE   800000
#define FIN  256
#define HD   128
#define EDIM 60
#define NEG_SLOPE 0.2f
#define SCANB 49
#define GTILES ((NN+127)/128)    // 391
#define ST 40                    // smem row stride (bf16 elems) to dodge bank conflicts

// ================= scratch =================
__device__ float d_h [NN*HD];
__device__ float d_z [NN*HD];
__device__ __nv_bfloat16 d_xh[NN*FIN], d_xl[NN*FIN];
__device__ __nv_bfloat16 d_gh[NN*HD],  d_gl[NN*HD];
__device__ __nv_bfloat16 d_wt1h[HD*FIN], d_wt1l[HD*FIN];   // [n][k] transposed W1
__device__ __nv_bfloat16 d_wt2h[HD*HD],  d_wt2l[HD*HD];
__device__ float d_as[NN], d_ad[NN];
__device__ float d_aE1[NE], d_aE2[NE];
__device__ float d_esum1[NN], d_esum2[NN];
__device__ int   d_deg[NN];
__device__ int   d_rows[NN];
__device__ int   d_bsum[SCANB];
__device__ int   d_boff[SCANB];
__device__ int   d_scandone = 0;
__device__ int   d_cursor[NN];
__device__ int   d_csr[NE];
__device__ __align__(16) float d_wvec1[EDIM];
__device__ __align__(16) float d_wvec2[EDIM];

__device__ __forceinline__ float lrelu(float v){ return v > 0.f ? v : NEG_SLOPE*v; }
__device__ __forceinline__ int startOf(int d){
    return (d == 0) ? 0 : d_rows[d-1] + d_boff[(d-1)>>10];
}

// ================= setup kernels =================
__global__ void k_pre(const float* __restrict__ We1, const float* __restrict__ ae1,
                      const float* __restrict__ We2, const float* __restrict__ ae2) {
    int i = blockIdx.x*blockDim.x + threadIdx.x;
    if (i < NN) { d_deg[i]=0; d_esum1[i]=0.f; d_esum2[i]=0.f; d_cursor[i]=0; }
    if (blockIdx.x == 0 && threadIdx.x < EDIM) {
        int j = threadIdx.x;
        float s1=0.f, s2=0.f;
        for (int c=0;c<HD;c++){ s1 += We1[j*HD+c]*ae1[c]; s2 += We2[j*HD+c]*ae2[c]; }
        d_wvec1[j]=s1; d_wvec2[j]=s2;
    }
}

// split x into bf16 hi/lo
__global__ void k_splitX(const float* __restrict__ x) {
    int i = blockIdx.x*blockDim.x + threadIdx.x;       // float4 index
    if (i*4 >= NN*FIN) return;
    float4 v = ((const float4*)x)[i];
    __nv_bfloat16 h0=__float2bfloat16(v.x), h1=__float2bfloat16(v.y),
                  h2=__float2bfloat16(v.z), h3=__float2bfloat16(v.w);
    __nv_bfloat16 l0=__float2bfloat16(v.x-__bfloat162float(h0)),
                  l1=__float2bfloat16(v.y-__bfloat162float(h1)),
                  l2=__float2bfloat16(v.z-__bfloat162float(h2)),
                  l3=__float2bfloat16(v.w-__bfloat162float(h3));
    __nv_bfloat162* xh2 = (__nv_bfloat162*)d_xh;
    __nv_bfloat162* xl2 = (__nv_bfloat162*)d_xl;
    xh2[i*2]   = __nv_bfloat162(h0,h1); xh2[i*2+1] = __nv_bfloat162(h2,h3);
    xl2[i*2]   = __nv_bfloat162(l0,l1); xl2[i*2+1] = __nv_bfloat162(l2,l3);
}

// transpose + split W1 (256x128) and W2 (128x128) into [n][k] bf16 hi/lo
__global__ void k_prepW(const float* __restrict__ W1, const float* __restrict__ W2) {
    int i = blockIdx.x*blockDim.x + threadIdx.x;
    if (i < FIN*HD) {
        int k = i >> 7, n = i & 127;
        float v = W1[i];
        __nv_bfloat16 hh = __float2bfloat16(v);
        d_wt1h[n*FIN+k] = hh;
        d_wt1l[n*FIN+k] = __float2bfloat16(v - __bfloat162float(hh));
    } else if (i < FIN*HD + HD*HD) {
        int j = i - FIN*HD;
        int k = j >> 7, n = j & 127;
        float v = W2[j];
        __nv_bfloat16 hh = __float2bfloat16(v);
        d_wt2h[n*HD+k] = hh;
        d_wt2l[n*HD+k] = __float2bfloat16(v - __bfloat162float(hh));
    }
}

// ================= edgedot: thread-per-edge, float4, no shuffles ==============
__global__ void __launch_bounds__(256) k_edgedot(const float* __restrict__ ef,
                                                 const int* __restrict__ dst) {
    __shared__ float4 w1[15], w2[15];
    int t = threadIdx.x;
    if (t < 15)            w1[t]    = ((const float4*)d_wvec1)[t];
    else if (t < 30)       w2[t-15] = ((const float4*)d_wvec2)[t-15];
    __syncthreads();
    int e = blockIdx.x*256 + t;
    if (e >= NE) return;
    const float4* row = (const float4*)(ef + (size_t)e*EDIM);   // 240B, 16B-aligned
    float v1 = 0.f, v2 = 0.f;
    #pragma unroll
    for (int k = 0; k < 15; k++) {
        float4 x = row[k];
        float4 a = w1[k], b = w2[k];
        v1 += x.x*a.x + x.y*a.y + x.z*a.z + x.w*a.w;
        v2 += x.x*b.x + x.y*b.y + x.z*b.z + x.w*b.w;
    }
    d_aE1[e] = v1;
    d_aE2[e] = v2;
    int dd = dst[e];
    atomicAdd(&d_esum1[dd], v1);
    atomicAdd(&d_esum2[dd], v2);
    atomicAdd(&d_deg[dd], 1);
}

__global__ void k_scan1() {
    __shared__ int sm[1024];
    __shared__ bool isLast;
    int b = blockIdx.x, t = threadIdx.x, i = b*1024 + t;
    int v = (i < NN) ? d_deg[i] : 0;
    sm[t]=v; __syncthreads();
    for (int o=1;o<1024;o<<=1){
        int ad = (t>=o) ? sm[t-o] : 0;
        __syncthreads(); sm[t]+=ad; __syncthreads();
    }
    if (i < NN) d_rows[i] = sm[t];
    if (t == 1023) d_bsum[b] = sm[1023];
    __threadfence();
    if (t == 0) isLast = (atomicAdd(&d_scandone, 1) == SCANB-1);
    __syncthreads();
    if (isLast && t == 0) {
        int run = 0;
        for (int q=0;q<SCANB;q++){ d_boff[q]=run; run += d_bsum[q]; }
        d_scandone = 0;
        __threadfence();
    }
}

__global__ void k_scatter(const int* __restrict__ dst) {
    int e = blockIdx.x*blockDim.x + threadIdx.x;
    if (e < NE) {
        int d = dst[e];
        d_csr[startOf(d) + atomicAdd(&d_cursor[d], 1)] = e;
    }
}

// ================= mma.sync bf16x3 GEMM (unchanged from R9) ===================
__device__ __forceinline__ void mma16816(float c[4], const uint32_t a[4], const uint32_t b[2]) {
    asm volatile("mma.sync.aligned.m16n8k16.row.col.f32.bf16.bf16.f32 "
        "{%0,%1,%2,%3}, {%4,%5,%6,%7}, {%8,%9}, {%0,%1,%2,%3};"
        : "+f"(c[0]), "+f"(c[1]), "+f"(c[2]), "+f"(c[3])
        : "r"(a[0]), "r"(a[1]), "r"(a[2]), "r"(a[3]), "r"(b[0]), "r"(b[1]));
}

__global__ void __launch_bounds__(256) k_hgemm(
        const __nv_bfloat16* __restrict__ Ah, const __nv_bfloat16* __restrict__ Al,
        const __nv_bfloat16* __restrict__ Bh, const __nv_bfloat16* __restrict__ Bl,
        float* __restrict__ C, int M, int KT) {
    __shared__ __nv_bfloat16 sAh[128*ST], sAl[128*ST];
    __shared__ __nv_bfloat16 sBh[128*ST], sBl[128*ST];
    int tid  = threadIdx.x;
    int wid  = tid >> 5, lane = tid & 31;
    int wm   = wid >> 1, wn = wid & 1;
    int r    = lane >> 2, t = lane & 3;
    int row0 = blockIdx.x * 128;

    float acc[2][8][4];
    #pragma unroll
    for (int mi=0;mi<2;mi++)
        #pragma unroll
        for (int ni=0;ni<8;ni++)
            #pragma unroll
            for (int q=0;q<4;q++) acc[mi][ni][q]=0.f;

    for (int k0 = 0; k0 < KT; k0 += 32) {
        #pragma unroll
        for (int it = 0; it < 2; it++) {
            int q   = tid + it*256;
            int row = q >> 2, cb = q & 3;
            int so  = row*ST + cb*8;
            size_t ao = (size_t)(row0+row)*KT + k0 + cb*8;
            uint4 vh = make_uint4(0,0,0,0), vl = vh;
            if (row0 + row < M) {
                vh = *(const uint4*)(Ah + ao);
                vl = *(const uint4*)(Al + ao);
            }
            *(uint4*)&sAh[so] = vh;
            *(uint4*)&sAl[so] = vl;
            size_t bo = (size_t)row*KT + k0 + cb*8;
            *(uint4*)&sBh[so] = *(const uint4*)(Bh + bo);
            *(uint4*)&sBl[so] = *(const uint4*)(Bl + bo);
        }
        __syncthreads();
        #pragma unroll
        for (int ks = 0; ks < 2; ks++) {
            int kb = ks*16 + 2*t;
            uint32_t ah[2][4], al[2][4], bh[8][2], bl[8][2];
            #pragma unroll
            for (int mi=0;mi<2;mi++){
                int rb = wm*32 + mi*16 + r;
                ah[mi][0] = *(const uint32_t*)&sAh[ rb    *ST + kb    ];
                ah[mi][1] = *(const uint32_t*)&sAh[(rb+8) *ST + kb    ];
                ah[mi][2] = *(const uint32_t*)&sAh[ rb    *ST + kb + 8];
                ah[mi][3] = *(const uint32_t*)&sAh[(rb+8) *ST + kb + 8];
                al[mi][0] = *(const uint32_t*)&sAl[ rb    *ST + kb    ];
                al[mi][1] = *(const uint32_t*)&sAl[(rb+8) *ST + kb    ];
                al[mi][2] = *(const uint32_t*)&sAl[ rb    *ST + kb + 8];
                al[mi][3] = *(const uint32_t*)&sAl[(rb+8) *ST + kb + 8];
            }
            #pragma unroll
            for (int ni=0;ni<8;ni++){
                int nb = wn*64 + ni*8 + r;
                bh[ni][0] = *(const uint32_t*)&sBh[nb*ST + kb    ];
                bh[ni][1] = *(const uint32_t*)&sBh[nb*ST + kb + 8];
                bl[ni][0] = *(const uint32_t*)&sBl[nb*ST + kb    ];
                bl[ni][1] = *(const uint32_t*)&sBl[nb*ST + kb + 8];
            }
            #pragma unroll
            for (int mi=0;mi<2;mi++)
                #pragma unroll
                for (int ni=0;ni<8;ni++){
                    mma16816(acc[mi][ni], ah[mi], bh[ni]);
                    mma16816(acc[mi][ni], al[mi], bh[ni]);
                    mma16816(acc[mi][ni], ah[mi], bl[ni]);
                }
        }
        __syncthreads();
    }
    #pragma unroll
    for (int mi=0;mi<2;mi++){
        int gr = row0 + wm*32 + mi*16 + r;
        #pragma unroll
        for (int ni=0;ni<8;ni++){
            int gc = wn*64 + ni*8 + 2*t;
            if (gr < M)
                *(float2*)&C[(size_t)gr*128 + gc]    = make_float2(acc[mi][ni][0], acc[mi][ni][1]);
            if (gr + 8 < M)
                *(float2*)&C[(size_t)(gr+8)*128 + gc] = make_float2(acc[mi][ni][2], acc[mi][ni][3]);
        }
    }
}

// ================= per-node attention scalars =================
__global__ void k_alpha(const float* __restrict__ h,
                        const float* __restrict__ asrc, const float* __restrict__ adst) {
    int node = blockIdx.x*8 + (threadIdx.x>>5);
    int lane = threadIdx.x & 31;
    if (node >= NN) return;
    const float* row = h + (size_t)node*HD;
    float s=0.f, d=0.f;
    #pragma unroll
    for (int q=0;q<4;q++){
        float v = row[lane+32*q];
        s += v*asrc[lane+32*q];
        d += v*adst[lane+32*q];
    }
    #pragma unroll
    for (int o=16;o;o>>=1){ s += __shfl_xor_sync(~0u,s,o); d += __shfl_xor_sync(~0u,d,o); }
    if (lane==0){ d_as[node]=s; d_ad[node]=d; }
}

// ================= aggregate (block-per-node; split-bf16 output for L1) =======
__global__ void __launch_bounds__(128) k_aggregate(
        const float* __restrict__ h, const float* __restrict__ aE,
        const float* __restrict__ esum, const int* __restrict__ srcArr,
        const float* __restrict__ bias, float* __restrict__ outF,
        __nv_bfloat16* __restrict__ outH, __nv_bfloat16* __restrict__ outL,
        int reluSplit) {
    int i = blockIdx.x;
    int t = threadIdx.x;
    __shared__ float sm_e[128];
    __shared__ int   sm_s[128];
    __shared__ float red[128];
    int r0   = startOf(i);
    int degi = d_deg[i];
    float adi = d_ad[i];
    float aself = lrelu(d_as[i] + adi + esum[i]/fmaxf((float)degi, 1.f));
    float m = aself;
    for (int j=t; j<degi; j+=128) {
        int e = d_csr[r0+j];
        m = fmaxf(m, lrelu(d_as[srcArr[e]] + adi + aE[e]));
    }
    red[t]=m; __syncthreads();
    #pragma unroll
    for (int o=64;o;o>>=1){ if (t<o) red[t]=fmaxf(red[t],red[t+o]); __syncthreads(); }
    m = red[0];
    __syncthreads();
    float acc = 0.f, dsum = 0.f;
    for (int j0=0; j0<degi; j0+=128) {
        int j = j0 + t;
        float ea = 0.f; int s = 0;
        if (j < degi) {
            int e = d_csr[r0+j];
            s = srcArr[e];
            ea = __expf(lrelu(d_as[s] + adi + aE[e]) - m);
        }
        sm_e[t]=ea; sm_s[t]=s;
        __syncthreads();
        int cnt = min(128, degi - j0);
        for (int q=0;q<cnt;q++){
            float c = sm_e[q];
            acc  += c * h[(size_t)sm_s[q]*HD + t];
            dsum += c;
        }
        __syncthreads();
    }
    float eself = __expf(aself - m);
    dsum += eself;
    acc  += eself * h[(size_t)i*HD + t];
    float o = acc/dsum + bias[t];
    size_t idx = (size_t)i*HD + t;
    if (reluSplit) {
        o = fmaxf(o, 0.f);
        __nv_bfloat16 hh = __float2bfloat16(o);
        outH[idx] = hh;
        outL[idx] = __float2bfloat16(o - __bfloat162float(hh));
    } else {
        outF[idx] = o;
    }
}

// ================= decode =================
__global__ void k_decode(const int* __restrict__ srcArr, const int* __restrict__ dstArr,
                         float* __restrict__ out) {
    int w    = blockIdx.x*8 + (threadIdx.x>>5);
    int lane = threadIdx.x & 31;
    if (w >= NE/2) return;
    const float4* z4 = (const float4*)d_z;
    float4 a1 = z4[(size_t)srcArr[w]*32 + lane];
    float4 b1 = z4[(size_t)dstArr[w]*32 + lane];
    float4 a2 = z4[(size_t)srcArr[w+NE/2]*32 + lane];
    float4 b2 = z4[(size_t)dstArr[w+NE/2]*32 + lane];
    float s = a1.x*b1.x + a1.y*b1.y + a1.z*b1.z + a1.w*b1.w
            + a2.x*b2.x + a2.y*b2.y + a2.z*b2.z + a2.w*b2.w;
    #pragma unroll
    for (int o=16;o;o>>=1) s += __shfl_down_sync(~0u,s,o);
    if (lane==0) out[w] = s;
}

// ================= launch =================
extern "C" void kernel_launch(void* const* d_in, const int* in_sizes, int n_in,
                              void* d_out, int out_size) {
    const float* x    = (const float*)d_in[0];
    const int*   ei   = (const int*)  d_in[1];
    const float* ef   = (const float*)d_in[2];
    const float* W1   = (const float*)d_in[4];
    const float* as1  = (const float*)d_in[5];
    const float* ad1  = (const float*)d_in[6];
    const float* We1  = (const float*)d_in[7];
    const float* ae1  = (const float*)d_in[8];
    const float* b1   = (const float*)d_in[9];
    const float* W2   = (const float*)d_in[10];
    const float* as2  = (const float*)d_in[11];
    const float* ad2  = (const float*)d_in[12];
    const float* We2  = (const float*)d_in[13];
    const float* ae2  = (const float*)d_in[14];
    const float* b2   = (const float*)d_in[15];
    const int* src = ei;
    const int* dst = ei + NE;

    float* h;   cudaGetSymbolAddress((void**)&h,   d_h);
    float* z;   cudaGetSymbolAddress((void**)&z,   d_z);
    float* aE1; cudaGetSymbolAddress((void**)&aE1, d_aE1);
    float* aE2; cudaGetSymbolAddress((void**)&aE2, d_aE2);
    float* es1; cudaGetSymbolAddress((void**)&es1, d_esum1);
    float* es2; cudaGetSymbolAddress((void**)&es2, d_esum2);
    __nv_bfloat16 *xh, *xl, *gh, *gl, *wt1h, *wt1l, *wt2h, *wt2l;
    cudaGetSymbolAddress((void**)&xh,  d_xh);
    cudaGetSymbolAddress((void**)&xl,  d_xl);
    cudaGetSymbolAddress((void**)&gh,  d_gh);
    cudaGetSymbolAddress((void**)&gl,  d_gl);
    cudaGetSymbolAddress((void**)&wt1h, d_wt1h);
    cudaGetSymbolAddress((void**)&wt1l, d_wt1l);
    cudaGetSymbolAddress((void**)&wt2h, d_wt2h);
    cudaGetSymbolAddress((void**)&wt2l, d_wt2l);

    k_pre<<<(NN+255)/256, 256>>>(We1, ae1, We2, ae2);
    k_splitX<<<(NN*FIN/4+255)/256, 256>>>(x);
    k_prepW<<<(FIN*HD + HD*HD + 255)/256, 256>>>(W1, W2);
    k_edgedot<<<(NE+255)/256, 256>>>(ef, dst);
    k_scan1<<<SCANB, 1024>>>();
    k_scatter<<<(NE+255)/256, 256>>>(dst);

    // layer 1
    k_hgemm<<<GTILES, 256>>>(xh, xl, wt1h, wt1l, h, NN, FIN);
    k_alpha<<<(NN+7)/8, 256>>>(h, as1, ad1);
    k_aggregate<<<NN, 128>>>(h, aE1, es1, src, b1, nullptr, gh, gl, 1);

    // layer 2
    k_hgemm<<<GTILES, 256>>>(gh, gl, wt2h, wt2l, h, NN, HD);
    k_alpha<<<(NN+7)/8, 256>>>(h, as2, ad2);
    k_aggregate<<<NN, 128>>>(h, aE2, es2, src, b2, z, nullptr, nullptr, 0);

    // decode
    k_decode<<<(NE/2+7)/8, 256>>>(src, dst, (float*)d_out);
}

// round 13
// speedup vs baseline: 1.8019x; 1.0377x over previous
#include <cuda_runtime.h>
#include <cuda_bf16.h>
#include <math.h>
#include <stdint.h>

#define NN   50000
#define NE   800000
#define FIN  256
#define HD   128
#define EDIM 60
#define NEG_SLOPE 0.2f
#define SCANB 49
#define GTILES ((NN+127)/128)    // 391
#define ST 40                    // hgemm smem row stride (bf16) to dodge bank conflicts

// ================= scratch =================
__device__ float d_h [NN*HD];
__device__ float d_z [NN*HD];
__device__ __nv_bfloat16 d_xh[NN*FIN], d_xl[NN*FIN];
__device__ __nv_bfloat16 d_gh[NN*HD],  d_gl[NN*HD];
__device__ __nv_bfloat16 d_wt1h[HD*FIN], d_wt1l[HD*FIN];   // [n][k] transposed W1
__device__ __nv_bfloat16 d_wt2h[HD*HD],  d_wt2l[HD*HD];
__device__ float d_as[NN], d_ad[NN];
__device__ float d_aE1[NE], d_aE2[NE];
__device__ float d_esum1[NN], d_esum2[NN];
__device__ int   d_deg[NN];
__device__ int   d_rows[NN];
__device__ int   d_bsum[SCANB];
__device__ int   d_boff[SCANB];
__device__ int   d_scandone = 0;
__device__ int   d_cursor[NN];
__device__ int   d_csr[NE];
__device__ __align__(16) float d_wvec1[EDIM];
__device__ __align__(16) float d_wvec2[EDIM];

__device__ __forceinline__ float lrelu(float v){ return v > 0.f ? v : NEG_SLOPE*v; }
__device__ __forceinline__ int startOf(int d){
    return (d == 0) ? 0 : d_rows[d-1] + d_boff[(d-1)>>10];
}

// ================= setup kernels =================
__global__ void k_pre(const float* __restrict__ We1, const float* __restrict__ ae1,
                      const float* __restrict__ We2, const float* __restrict__ ae2) {
    int i = blockIdx.x*blockDim.x + threadIdx.x;
    if (i < NN) { d_deg[i]=0; d_esum1[i]=0.f; d_esum2[i]=0.f; d_cursor[i]=0; }
    if (blockIdx.x == 0 && threadIdx.x < EDIM) {
        int j = threadIdx.x;
        float s1=0.f, s2=0.f;
        for (int c=0;c<HD;c++){ s1 += We1[j*HD+c]*ae1[c]; s2 += We2[j*HD+c]*ae2[c]; }
        d_wvec1[j]=s1; d_wvec2[j]=s2;
    }
}

// split x into bf16 hi/lo
__global__ void k_splitX(const float* __restrict__ x) {
    int i = blockIdx.x*blockDim.x + threadIdx.x;       // float4 index
    if (i*4 >= NN*FIN) return;
    float4 v = ((const float4*)x)[i];
    __nv_bfloat16 h0=__float2bfloat16(v.x), h1=__float2bfloat16(v.y),
                  h2=__float2bfloat16(v.z), h3=__float2bfloat16(v.w);
    __nv_bfloat16 l0=__float2bfloat16(v.x-__bfloat162float(h0)),
                  l1=__float2bfloat16(v.y-__bfloat162float(h1)),
                  l2=__float2bfloat16(v.z-__bfloat162float(h2)),
                  l3=__float2bfloat16(v.w-__bfloat162float(h3));
    __nv_bfloat162* xh2 = (__nv_bfloat162*)d_xh;
    __nv_bfloat162* xl2 = (__nv_bfloat162*)d_xl;
    xh2[i*2]   = __nv_bfloat162(h0,h1); xh2[i*2+1] = __nv_bfloat162(h2,h3);
    xl2[i*2]   = __nv_bfloat162(l0,l1); xl2[i*2+1] = __nv_bfloat162(l2,l3);
}

// transpose + split W1 (256x128) and W2 (128x128) into [n][k] bf16 hi/lo
__global__ void k_prepW(const float* __restrict__ W1, const float* __restrict__ W2) {
    int i = blockIdx.x*blockDim.x + threadIdx.x;
    if (i < FIN*HD) {
        int k = i >> 7, n = i & 127;
        float v = W1[i];
        __nv_bfloat16 hh = __float2bfloat16(v);
        d_wt1h[n*FIN+k] = hh;
        d_wt1l[n*FIN+k] = __float2bfloat16(v - __bfloat162float(hh));
    } else if (i < FIN*HD + HD*HD) {
        int j = i - FIN*HD;
        int k = j >> 7, n = j & 127;
        float v = W2[j];
        __nv_bfloat16 hh = __float2bfloat16(v);
        d_wt2h[n*HD+k] = hh;
        d_wt2l[n*HD+k] = __float2bfloat16(v - __bfloat162float(hh));
    }
}

// ================= edgedot: 128 thr / 128 edges, coalesced smem transpose =====
// Phase 1: block loads its 128 contiguous rows (30720 B) as coalesced float4s,
// scatter-stores into tile[edge][61] (61-stride -> conflict-free columns).
// Phase 2: thread t computes both dots for edge t from smem (scalar LDS,
// broadcast weights), then writes aE + 3 atomics.
#define EPB 128
__global__ void __launch_bounds__(EPB) k_edgedot(const float* __restrict__ ef,
                                                 const int* __restrict__ dst) {
    __shared__ float tile[EPB*61];
    __shared__ float w1s[EDIM], w2s[EDIM];
    int t = threadIdx.x;
    if (t < EDIM)            w1s[t]        = d_wvec1[t];
    else if (t < 2*EDIM)     w2s[t-EDIM]   = d_wvec2[t-EDIM];
    int e0 = blockIdx.x * EPB;
    const float4* g4 = (const float4*)(ef + (size_t)e0*EDIM);   // block-contiguous
    #pragma unroll
    for (int i = 0; i < 15; i++) {
        int j = t + i*EPB;                // 0..1919
        float4 v = g4[j];
        int el = j / 15, k4 = j % 15;     // edge-local, float4-within-row
        float* dsti = &tile[el*61 + k4*4];
        dsti[0]=v.x; dsti[1]=v.y; dsti[2]=v.z; dsti[3]=v.w;
    }
    __syncthreads();
    const float* row = &tile[t*61];
    float v1 = 0.f, v2 = 0.f;
    #pragma unroll
    for (int k = 0; k < EDIM; k++) {
        float x = row[k];
        v1 += x * w1s[k];
        v2 += x * w2s[k];
    }
    int e = e0 + t;
    d_aE1[e] = v1;
    d_aE2[e] = v2;
    int dd = dst[e];
    atomicAdd(&d_esum1[dd], v1);
    atomicAdd(&d_esum2[dd], v2);
    atomicAdd(&d_deg[dd], 1);
}

__global__ void k_scan1() {
    __shared__ int sm[1024];
    __shared__ bool isLast;
    int b = blockIdx.x, t = threadIdx.x, i = b*1024 + t;
    int v = (i < NN) ? d_deg[i] : 0;
    sm[t]=v; __syncthreads();
    for (int o=1;o<1024;o<<=1){
        int ad = (t>=o) ? sm[t-o] : 0;
        __syncthreads(); sm[t]+=ad; __syncthreads();
    }
    if (i < NN) d_rows[i] = sm[t];
    if (t == 1023) d_bsum[b] = sm[1023];
    __threadfence();
    if (t == 0) isLast = (atomicAdd(&d_scandone, 1) == SCANB-1);
    __syncthreads();
    if (isLast && t == 0) {
        int run = 0;
        for (int q=0;q<SCANB;q++){ d_boff[q]=run; run += d_bsum[q]; }
        d_scandone = 0;
        __threadfence();
    }
}

__global__ void k_scatter(const int* __restrict__ dst) {
    int e = blockIdx.x*blockDim.x + threadIdx.x;
    if (e < NE) {
        int d = dst[e];
        d_csr[startOf(d) + atomicAdd(&d_cursor[d], 1)] = e;
    }
}

// ================= mma.sync bf16x3 GEMM (unchanged) ===========================
__device__ __forceinline__ void mma16816(float c[4], const uint32_t a[4], const uint32_t b[2]) {
    asm volatile("mma.sync.aligned.m16n8k16.row.col.f32.bf16.bf16.f32 "
        "{%0,%1,%2,%3}, {%4,%5,%6,%7}, {%8,%9}, {%0,%1,%2,%3};"
        : "+f"(c[0]), "+f"(c[1]), "+f"(c[2]), "+f"(c[3])
        : "r"(a[0]), "r"(a[1]), "r"(a[2]), "r"(a[3]), "r"(b[0]), "r"(b[1]));
}

__global__ void __launch_bounds__(256) k_hgemm(
        const __nv_bfloat16* __restrict__ Ah, const __nv_bfloat16* __restrict__ Al,
        const __nv_bfloat16* __restrict__ Bh, const __nv_bfloat16* __restrict__ Bl,
        float* __restrict__ C, int M, int KT) {
    __shared__ __nv_bfloat16 sAh[128*ST], sAl[128*ST];
    __shared__ __nv_bfloat16 sBh[128*ST], sBl[128*ST];
    int tid  = threadIdx.x;
    int wid  = tid >> 5, lane = tid & 31;
    int wm   = wid >> 1, wn = wid & 1;
    int r    = lane >> 2, t = lane & 3;
    int row0 = blockIdx.x * 128;

    float acc[2][8][4];
    #pragma unroll
    for (int mi=0;mi<2;mi++)
        #pragma unroll
        for (int ni=0;ni<8;ni++)
            #pragma unroll
            for (int q=0;q<4;q++) acc[mi][ni][q]=0.f;

    for (int k0 = 0; k0 < KT; k0 += 32) {
        #pragma unroll
        for (int it = 0; it < 2; it++) {
            int q   = tid + it*256;
            int row = q >> 2, cb = q & 3;
            int so  = row*ST + cb*8;
            size_t ao = (size_t)(row0+row)*KT + k0 + cb*8;
            uint4 vh = make_uint4(0,0,0,0), vl = vh;
            if (row0 + row < M) {
                vh = *(const uint4*)(Ah + ao);
                vl = *(const uint4*)(Al + ao);
            }
            *(uint4*)&sAh[so] = vh;
            *(uint4*)&sAl[so] = vl;
            size_t bo = (size_t)row*KT + k0 + cb*8;
            *(uint4*)&sBh[so] = *(const uint4*)(Bh + bo);
            *(uint4*)&sBl[so] = *(const uint4*)(Bl + bo);
        }
        __syncthreads();
        #pragma unroll
        for (int ks = 0; ks < 2; ks++) {
            int kb = ks*16 + 2*t;
            uint32_t ah[2][4], al[2][4], bh[8][2], bl[8][2];
            #pragma unroll
            for (int mi=0;mi<2;mi++){
                int rb = wm*32 + mi*16 + r;
                ah[mi][0] = *(const uint32_t*)&sAh[ rb    *ST + kb    ];
                ah[mi][1] = *(const uint32_t*)&sAh[(rb+8) *ST + kb    ];
                ah[mi][2] = *(const uint32_t*)&sAh[ rb    *ST + kb + 8];
                ah[mi][3] = *(const uint32_t*)&sAh[(rb+8) *ST + kb + 8];
                al[mi][0] = *(const uint32_t*)&sAl[ rb    *ST + kb    ];
                al[mi][1] = *(const uint32_t*)&sAl[(rb+8) *ST + kb    ];
                al[mi][2] = *(const uint32_t*)&sAl[ rb    *ST + kb + 8];
                al[mi][3] = *(const uint32_t*)&sAl[(rb+8) *ST + kb + 8];
            }
            #pragma unroll
            for (int ni=0;ni<8;ni++){
                int nb = wn*64 + ni*8 + r;
                bh[ni][0] = *(const uint32_t*)&sBh[nb*ST + kb    ];
                bh[ni][1] = *(const uint32_t*)&sBh[nb*ST + kb + 8];
                bl[ni][0] = *(const uint32_t*)&sBl[nb*ST + kb    ];
                bl[ni][1] = *(const uint32_t*)&sBl[nb*ST + kb + 8];
            }
            #pragma unroll
            for (int mi=0;mi<2;mi++)
                #pragma unroll
                for (int ni=0;ni<8;ni++){
                    mma16816(acc[mi][ni], ah[mi], bh[ni]);
                    mma16816(acc[mi][ni], al[mi], bh[ni]);
                    mma16816(acc[mi][ni], ah[mi], bl[ni]);
                }
        }
        __syncthreads();
    }
    #pragma unroll
    for (int mi=0;mi<2;mi++){
        int gr = row0 + wm*32 + mi*16 + r;
        #pragma unroll
        for (int ni=0;ni<8;ni++){
            int gc = wn*64 + ni*8 + 2*t;
            if (gr < M)
                *(float2*)&C[(size_t)gr*128 + gc]    = make_float2(acc[mi][ni][0], acc[mi][ni][1]);
            if (gr + 8 < M)
                *(float2*)&C[(size_t)(gr+8)*128 + gc] = make_float2(acc[mi][ni][2], acc[mi][ni][3]);
        }
    }
}

// ================= per-node attention scalars =================
__global__ void k_alpha(const float* __restrict__ h,
                        const float* __restrict__ asrc, const float* __restrict__ adst) {
    int node = blockIdx.x*8 + (threadIdx.x>>5);
    int lane = threadIdx.x & 31;
    if (node >= NN) return;
    const float* row = h + (size_t)node*HD;
    float s=0.f, d=0.f;
    #pragma unroll
    for (int q=0;q<4;q++){
        float v = row[lane+32*q];
        s += v*asrc[lane+32*q];
        d += v*adst[lane+32*q];
    }
    #pragma unroll
    for (int o=16;o;o>>=1){ s += __shfl_xor_sync(~0u,s,o); d += __shfl_xor_sync(~0u,d,o); }
    if (lane==0){ d_as[node]=s; d_ad[node]=d; }
}

// ================= aggregate (block-per-node; split-bf16 output for L1) =======
__global__ void __launch_bounds__(128) k_aggregate(
        const float* __restrict__ h, const float* __restrict__ aE,
        const float* __restrict__ esum, const int* __restrict__ srcArr,
        const float* __restrict__ bias, float* __restrict__ outF,
        __nv_bfloat16* __restrict__ outH, __nv_bfloat16* __restrict__ outL,
        int reluSplit) {
    int i = blockIdx.x;
    int t = threadIdx.x;
    __shared__ float sm_e[128];
    __shared__ int   sm_s[128];
    __shared__ float red[128];
    int r0   = startOf(i);
    int degi = d_deg[i];
    float adi = d_ad[i];
    float aself = lrelu(d_as[i] + adi + esum[i]/fmaxf((float)degi, 1.f));
    float m = aself;
    for (int j=t; j<degi; j+=128) {
        int e = d_csr[r0+j];
        m = fmaxf(m, lrelu(d_as[srcArr[e]] + adi + aE[e]));
    }
    red[t]=m; __syncthreads();
    #pragma unroll
    for (int o=64;o;o>>=1){ if (t<o) red[t]=fmaxf(red[t],red[t+o]); __syncthreads(); }
    m = red[0];
    __syncthreads();
    float acc = 0.f, dsum = 0.f;
    for (int j0=0; j0<degi; j0+=128) {
        int j = j0 + t;
        float ea = 0.f; int s = 0;
        if (j < degi) {
            int e = d_csr[r0+j];
            s = srcArr[e];
            ea = __expf(lrelu(d_as[s] + adi + aE[e]) - m);
        }
        sm_e[t]=ea; sm_s[t]=s;
        __syncthreads();
        int cnt = min(128, degi - j0);
        for (int q=0;q<cnt;q++){
            float c = sm_e[q];
            acc  += c * h[(size_t)sm_s[q]*HD + t];
            dsum += c;
        }
        __syncthreads();
    }
    float eself = __expf(aself - m);
    dsum += eself;
    acc  += eself * h[(size_t)i*HD + t];
    float o = acc/dsum + bias[t];
    size_t idx = (size_t)i*HD + t;
    if (reluSplit) {
        o = fmaxf(o, 0.f);
        __nv_bfloat16 hh = __float2bfloat16(o);
        outH[idx] = hh;
        outL[idx] = __float2bfloat16(o - __bfloat162float(hh));
    } else {
        outF[idx] = o;
    }
}

// ================= decode =================
__global__ void k_decode(const int* __restrict__ srcArr, const int* __restrict__ dstArr,
                         float* __restrict__ out) {
    int w    = blockIdx.x*8 + (threadIdx.x>>5);
    int lane = threadIdx.x & 31;
    if (w >= NE/2) return;
    const float4* z4 = (const float4*)d_z;
    float4 a1 = z4[(size_t)srcArr[w]*32 + lane];
    float4 b1 = z4[(size_t)dstArr[w]*32 + lane];
    float4 a2 = z4[(size_t)srcArr[w+NE/2]*32 + lane];
    float4 b2 = z4[(size_t)dstArr[w+NE/2]*32 + lane];
    float s = a1.x*b1.x + a1.y*b1.y + a1.z*b1.z + a1.w*b1.w
            + a2.x*b2.x + a2.y*b2.y + a2.z*b2.z + a2.w*b2.w;
    #pragma unroll
    for (int o=16;o;o>>=1) s += __shfl_down_sync(~0u,s,o);
    if (lane==0) out[w] = s;
}

// ================= launch =================
extern "C" void kernel_launch(void* const* d_in, const int* in_sizes, int n_in,
                              void* d_out, int out_size) {
    const float* x    = (const float*)d_in[0];
    const int*   ei   = (const int*)  d_in[1];
    const float* ef   = (const float*)d_in[2];
    const float* W1   = (const float*)d_in[4];
    const float* as1  = (const float*)d_in[5];
    const float* ad1  = (const float*)d_in[6];
    const float* We1  = (const float*)d_in[7];
    const float* ae1  = (const float*)d_in[8];
    const float* b1   = (const float*)d_in[9];
    const float* W2   = (const float*)d_in[10];
    const float* as2  = (const float*)d_in[11];
    const float* ad2  = (const float*)d_in[12];
    const float* We2  = (const float*)d_in[13];
    const float* ae2  = (const float*)d_in[14];
    const float* b2   = (const float*)d_in[15];
    const int* src = ei;
    const int* dst = ei + NE;

    float* h;   cudaGetSymbolAddress((void**)&h,   d_h);
    float* z;   cudaGetSymbolAddress((void**)&z,   d_z);
    float* aE1; cudaGetSymbolAddress((void**)&aE1, d_aE1);
    float* aE2; cudaGetSymbolAddress((void**)&aE2, d_aE2);
    float* es1; cudaGetSymbolAddress((void**)&es1, d_esum1);
    float* es2; cudaGetSymbolAddress((void**)&es2, d_esum2);
    __nv_bfloat16 *xh, *xl, *gh, *gl, *wt1h, *wt1l, *wt2h, *wt2l;
    cudaGetSymbolAddress((void**)&xh,  d_xh);
    cudaGetSymbolAddress((void**)&xl,  d_xl);
    cudaGetSymbolAddress((void**)&gh,  d_gh);
    cudaGetSymbolAddress((void**)&gl,  d_gl);
    cudaGetSymbolAddress((void**)&wt1h, d_wt1h);
    cudaGetSymbolAddress((void**)&wt1l, d_wt1l);
    cudaGetSymbolAddress((void**)&wt2h, d_wt2h);
    cudaGetSymbolAddress((void**)&wt2l, d_wt2l);

    k_pre<<<(NN+255)/256, 256>>>(We1, ae1, We2, ae2);
    k_splitX<<<(NN*FIN/4+255)/256, 256>>>(x);
    k_prepW<<<(FIN*HD + HD*HD + 255)/256, 256>>>(W1, W2);
    k_edgedot<<<NE/EPB, EPB>>>(ef, dst);
    k_scan1<<<SCANB, 1024>>>();
    k_scatter<<<(NE+255)/256, 256>>>(dst);

    // layer 1
    k_hgemm<<<GTILES, 256>>>(xh, xl, wt1h, wt1l, h, NN, FIN);
    k_alpha<<<(NN+7)/8, 256>>>(h, as1, ad1);
    k_aggregate<<<NN, 128>>>(h, aE1, es1, src, b1, nullptr, gh, gl, 1);

    // layer 2
    k_hgemm<<<GTILES, 256>>>(gh, gl, wt2h, wt2l, h, NN, HD);
    k_alpha<<<(NN+7)/8, 256>>>(h, as2, ad2);
    k_aggregate<<<NN, 128>>>(h, aE2, es2, src, b2, z, nullptr, nullptr, 0);

    // decode
    k_decode<<<(NE/2+7)/8, 256>>>(src, dst, (float*)d_out);
}

// round 16
// speedup vs baseline: 1.8723x; 1.0391x over previous
#include <cuda_runtime.h>
#include <cuda_bf16.h>
#include <math.h>
#include <stdint.h>

#define NN   50000
#define NE   800000
#define FIN  256
#define HD   128
#define EDIM 60
#define NEG_SLOPE 0.2f
#define SCANB 49
#define GTILES ((NN+127)/128)    // 391
#define ST 40                    // hgemm smem row stride (bf16) to dodge bank conflicts

// ================= scratch =================
__device__ float d_h [NN*HD];
__device__ float d_z [NN*HD];
__device__ __nv_bfloat16 d_xh[NN*FIN], d_xl[NN*FIN];
__device__ __nv_bfloat16 d_gh[NN*HD],  d_gl[NN*HD];
__device__ __nv_bfloat16 d_wt1h[HD*FIN], d_wt1l[HD*FIN];   // [n][k] transposed W1
__device__ __nv_bfloat16 d_wt2h[HD*HD],  d_wt2l[HD*HD];
__device__ float d_as[NN], d_ad[NN];
__device__ float d_aE1[NE], d_aE2[NE];
__device__ float d_esum1[NN], d_esum2[NN];
__device__ int   d_deg[NN];
__device__ int   d_rows[NN];
__device__ int   d_bsum[SCANB];
__device__ int   d_boff[SCANB];
__device__ int   d_scandone = 0;
__device__ int   d_cursor[NN];
__device__ int   d_csr[NE];
__device__ __align__(16) float d_wvec1[EDIM];
__device__ __align__(16) float d_wvec2[EDIM];

__device__ __forceinline__ float lrelu(float v){ return v > 0.f ? v : NEG_SLOPE*v; }
__device__ __forceinline__ int startOf(int d){
    return (d == 0) ? 0 : d_rows[d-1] + d_boff[(d-1)>>10];
}

// ================= setup kernels =================
__global__ void k_pre(const float* __restrict__ We1, const float* __restrict__ ae1,
                      const float* __restrict__ We2, const float* __restrict__ ae2) {
    int i = blockIdx.x*blockDim.x + threadIdx.x;
    if (i < NN) { d_deg[i]=0; d_esum1[i]=0.f; d_esum2[i]=0.f; d_cursor[i]=0; }
    if (blockIdx.x == 0 && threadIdx.x < EDIM) {
        int j = threadIdx.x;
        float s1=0.f, s2=0.f;
        for (int c=0;c<HD;c++){ s1 += We1[j*HD+c]*ae1[c]; s2 += We2[j*HD+c]*ae2[c]; }
        d_wvec1[j]=s1; d_wvec2[j]=s2;
    }
}

// split x into bf16 hi/lo
__global__ void k_splitX(const float* __restrict__ x) {
    int i = blockIdx.x*blockDim.x + threadIdx.x;       // float4 index
    if (i*4 >= NN*FIN) return;
    float4 v = ((const float4*)x)[i];
    __nv_bfloat16 h0=__float2bfloat16(v.x), h1=__float2bfloat16(v.y),
                  h2=__float2bfloat16(v.z), h3=__float2bfloat16(v.w);
    __nv_bfloat16 l0=__float2bfloat16(v.x-__bfloat162float(h0)),
                  l1=__float2bfloat16(v.y-__bfloat162float(h1)),
                  l2=__float2bfloat16(v.z-__bfloat162float(h2)),
                  l3=__float2bfloat16(v.w-__bfloat162float(h3));
    __nv_bfloat162* xh2 = (__nv_bfloat162*)d_xh;
    __nv_bfloat162* xl2 = (__nv_bfloat162*)d_xl;
    xh2[i*2]   = __nv_bfloat162(h0,h1); xh2[i*2+1] = __nv_bfloat162(h2,h3);
    xl2[i*2]   = __nv_bfloat162(l0,l1); xl2[i*2+1] = __nv_bfloat162(l2,l3);
}

// transpose + split W1 (256x128) and W2 (128x128) into [n][k] bf16 hi/lo
__global__ void k_prepW(const float* __restrict__ W1, const float* __restrict__ W2) {
    int i = blockIdx.x*blockDim.x + threadIdx.x;
    if (i < FIN*HD) {
        int k = i >> 7, n = i & 127;
        float v = W1[i];
        __nv_bfloat16 hh = __float2bfloat16(v);
        d_wt1h[n*FIN+k] = hh;
        d_wt1l[n*FIN+k] = __float2bfloat16(v - __bfloat162float(hh));
    } else if (i < FIN*HD + HD*HD) {
        int j = i - FIN*HD;
        int k = j >> 7, n = j & 127;
        float v = W2[j];
        __nv_bfloat16 hh = __float2bfloat16(v);
        d_wt2h[n*HD+k] = hh;
        d_wt2l[n*HD+k] = __float2bfloat16(v - __bfloat162float(hh));
    }
}

// ================= edgedot: coalesced smem transpose, reg-capped ==============
// Phase 1 staged in 3 groups of 5 float4s (<=20 floats live) so regs stay under
// the __launch_bounds__(128,12) cap (42) -> ~75% occupancy.
#define EPB 128
__global__ void __launch_bounds__(EPB, 12) k_edgedot(const float* __restrict__ ef,
                                                     const int* __restrict__ dst) {
    __shared__ float tile[EPB*61];
    __shared__ float w1s[EDIM], w2s[EDIM];
    int t = threadIdx.x;
    if (t < EDIM)            w1s[t]        = d_wvec1[t];
    else if (t < 2*EDIM)     w2s[t-EDIM]   = d_wvec2[t-EDIM];
    int e0 = blockIdx.x * EPB;
    const float4* g4 = (const float4*)(ef + (size_t)e0*EDIM);   // block-contiguous
    #pragma unroll
    for (int g = 0; g < 3; g++) {
        float4 v[5];
        #pragma unroll
        for (int i = 0; i < 5; i++) v[i] = g4[t + (g*5+i)*EPB];
        #pragma unroll
        for (int i = 0; i < 5; i++) {
            int j = t + (g*5+i)*EPB;          // 0..1919
            int el = j / 15, k4 = j % 15;     // edge-local, float4-within-row
            float* dsti = &tile[el*61 + k4*4];
            dsti[0]=v[i].x; dsti[1]=v[i].y; dsti[2]=v[i].z; dsti[3]=v[i].w;
        }
    }
    __syncthreads();
    const float* row = &tile[t*61];
    float v1 = 0.f, v2 = 0.f;
    #pragma unroll
    for (int k = 0; k < EDIM; k++) {
        float x = row[k];
        v1 += x * w1s[k];
        v2 += x * w2s[k];
    }
    int e = e0 + t;
    d_aE1[e] = v1;
    d_aE2[e] = v2;
    int dd = dst[e];
    atomicAdd(&d_esum1[dd], v1);
    atomicAdd(&d_esum2[dd], v2);
    atomicAdd(&d_deg[dd], 1);
}

__global__ void k_scan1() {
    __shared__ int sm[1024];
    __shared__ bool isLast;
    int b = blockIdx.x, t = threadIdx.x, i = b*1024 + t;
    int v = (i < NN) ? d_deg[i] : 0;
    sm[t]=v; __syncthreads();
    for (int o=1;o<1024;o<<=1){
        int ad = (t>=o) ? sm[t-o] : 0;
        __syncthreads(); sm[t]+=ad; __syncthreads();
    }
    if (i < NN) d_rows[i] = sm[t];
    if (t == 1023) d_bsum[b] = sm[1023];
    __threadfence();
    if (t == 0) isLast = (atomicAdd(&d_scandone, 1) == SCANB-1);
    __syncthreads();
    if (isLast && t == 0) {
        int run = 0;
        for (int q=0;q<SCANB;q++){ d_boff[q]=run; run += d_bsum[q]; }
        d_scandone = 0;
        __threadfence();
    }
}

__global__ void k_scatter(const int* __restrict__ dst) {
    int e = blockIdx.x*blockDim.x + threadIdx.x;
    if (e < NE) {
        int d = dst[e];
        d_csr[startOf(d) + atomicAdd(&d_cursor[d], 1)] = e;
    }
}

// ================= mma.sync bf16x3 GEMM (unchanged) ===========================
__device__ __forceinline__ void mma16816(float c[4], const uint32_t a[4], const uint32_t b[2]) {
    asm volatile("mma.sync.aligned.m16n8k16.row.col.f32.bf16.bf16.f32 "
        "{%0,%1,%2,%3}, {%4,%5,%6,%7}, {%8,%9}, {%0,%1,%2,%3};"
        : "+f"(c[0]), "+f"(c[1]), "+f"(c[2]), "+f"(c[3])
        : "r"(a[0]), "r"(a[1]), "r"(a[2]), "r"(a[3]), "r"(b[0]), "r"(b[1]));
}

__global__ void __launch_bounds__(256) k_hgemm(
        const __nv_bfloat16* __restrict__ Ah, const __nv_bfloat16* __restrict__ Al,
        const __nv_bfloat16* __restrict__ Bh, const __nv_bfloat16* __restrict__ Bl,
        float* __restrict__ C, int M, int KT) {
    __shared__ __nv_bfloat16 sAh[128*ST], sAl[128*ST];
    __shared__ __nv_bfloat16 sBh[128*ST], sBl[128*ST];
    int tid  = threadIdx.x;
    int wid  = tid >> 5, lane = tid & 31;
    int wm   = wid >> 1, wn = wid & 1;
    int r    = lane >> 2, t = lane & 3;
    int row0 = blockIdx.x * 128;

    float acc[2][8][4];
    #pragma unroll
    for (int mi=0;mi<2;mi++)
        #pragma unroll
        for (int ni=0;ni<8;ni++)
            #pragma unroll
            for (int q=0;q<4;q++) acc[mi][ni][q]=0.f;

    for (int k0 = 0; k0 < KT; k0 += 32) {
        #pragma unroll
        for (int it = 0; it < 2; it++) {
            int q   = tid + it*256;
            int row = q >> 2, cb = q & 3;
            int so  = row*ST + cb*8;
            size_t ao = (size_t)(row0+row)*KT + k0 + cb*8;
            uint4 vh = make_uint4(0,0,0,0), vl = vh;
            if (row0 + row < M) {
                vh = *(const uint4*)(Ah + ao);
                vl = *(const uint4*)(Al + ao);
            }
            *(uint4*)&sAh[so] = vh;
            *(uint4*)&sAl[so] = vl;
            size_t bo = (size_t)row*KT + k0 + cb*8;
            *(uint4*)&sBh[so] = *(const uint4*)(Bh + bo);
            *(uint4*)&sBl[so] = *(const uint4*)(Bl + bo);
        }
        __syncthreads();
        #pragma unroll
        for (int ks = 0; ks < 2; ks++) {
            int kb = ks*16 + 2*t;
            uint32_t ah[2][4], al[2][4], bh[8][2], bl[8][2];
            #pragma unroll
            for (int mi=0;mi<2;mi++){
                int rb = wm*32 + mi*16 + r;
                ah[mi][0] = *(const uint32_t*)&sAh[ rb    *ST + kb    ];
                ah[mi][1] = *(const uint32_t*)&sAh[(rb+8) *ST + kb    ];
                ah[mi][2] = *(const uint32_t*)&sAh[ rb    *ST + kb + 8];
                ah[mi][3] = *(const uint32_t*)&sAh[(rb+8) *ST + kb + 8];
                al[mi][0] = *(const uint32_t*)&sAl[ rb    *ST + kb    ];
                al[mi][1] = *(const uint32_t*)&sAl[(rb+8) *ST + kb    ];
                al[mi][2] = *(const uint32_t*)&sAl[ rb    *ST + kb + 8];
                al[mi][3] = *(const uint32_t*)&sAl[(rb+8) *ST + kb + 8];
            }
            #pragma unroll
            for (int ni=0;ni<8;ni++){
                int nb = wn*64 + ni*8 + r;
                bh[ni][0] = *(const uint32_t*)&sBh[nb*ST + kb    ];
                bh[ni][1] = *(const uint32_t*)&sBh[nb*ST + kb + 8];
                bl[ni][0] = *(const uint32_t*)&sBl[nb*ST + kb    ];
                bl[ni][1] = *(const uint32_t*)&sBl[nb*ST + kb + 8];
            }
            #pragma unroll
            for (int mi=0;mi<2;mi++)
                #pragma unroll
                for (int ni=0;ni<8;ni++){
                    mma16816(acc[mi][ni], ah[mi], bh[ni]);
                    mma16816(acc[mi][ni], al[mi], bh[ni]);
                    mma16816(acc[mi][ni], ah[mi], bl[ni]);
                }
        }
        __syncthreads();
    }
    #pragma unroll
    for (int mi=0;mi<2;mi++){
        int gr = row0 + wm*32 + mi*16 + r;
        #pragma unroll
        for (int ni=0;ni<8;ni++){
            int gc = wn*64 + ni*8 + 2*t;
            if (gr < M)
                *(float2*)&C[(size_t)gr*128 + gc]    = make_float2(acc[mi][ni][0], acc[mi][ni][1]);
            if (gr + 8 < M)
                *(float2*)&C[(size_t)(gr+8)*128 + gc] = make_float2(acc[mi][ni][2], acc[mi][ni][3]);
        }
    }
}

// ================= per-node attention scalars =================
__global__ void k_alpha(const float* __restrict__ h,
                        const float* __restrict__ asrc, const float* __restrict__ adst) {
    int node = blockIdx.x*8 + (threadIdx.x>>5);
    int lane = threadIdx.x & 31;
    if (node >= NN) return;
    const float* row = h + (size_t)node*HD;
    float s=0.f, d=0.f;
    #pragma unroll
    for (int q=0;q<4;q++){
        float v = row[lane+32*q];
        s += v*asrc[lane+32*q];
        d += v*adst[lane+32*q];
    }
    #pragma unroll
    for (int o=16;o;o>>=1){ s += __shfl_xor_sync(~0u,s,o); d += __shfl_xor_sync(~0u,d,o); }
    if (lane==0){ d_as[node]=s; d_ad[node]=d; }
}

// ================= aggregate: single-pass alpha cache for first 128 nbrs ======
__global__ void __launch_bounds__(128) k_aggregate(
        const float* __restrict__ h, const float* __restrict__ aE,
        const float* __restrict__ esum, const int* __restrict__ srcArr,
        const float* __restrict__ bias, float* __restrict__ outF,
        __nv_bfloat16* __restrict__ outH, __nv_bfloat16* __restrict__ outL,
        int reluSplit) {
    int i = blockIdx.x;
    int t = threadIdx.x;
    __shared__ float sm_e[128];
    __shared__ int   sm_s[128];
    __shared__ float red[128];
    int r0   = startOf(i);
    int degi = d_deg[i];
    float adi = d_ad[i];
    float aself = lrelu(d_as[i] + adi + esum[i]/fmaxf((float)degi, 1.f));
    // pass 1: compute+cache alpha for first 128 neighbors; strided max for the rest
    float m = aself;
    if (t < degi) {
        int e = d_csr[r0+t];
        int s = srcArr[e];
        float a = lrelu(d_as[s] + adi + aE[e]);
        sm_e[t] = a; sm_s[t] = s;
        m = fmaxf(m, a);
    }
    for (int j=t+128; j<degi; j+=128) {
        int e = d_csr[r0+j];
        m = fmaxf(m, lrelu(d_as[srcArr[e]] + adi + aE[e]));
    }
    red[t]=m; __syncthreads();
    #pragma unroll
    for (int o=64;o;o>>=1){ if (t<o) red[t]=fmaxf(red[t],red[t+o]); __syncthreads(); }
    m = red[0];
    __syncthreads();
    // chunk 0: exp cached alphas in place
    if (t < degi) sm_e[t] = __expf(sm_e[t] - m);
    __syncthreads();
    float acc = 0.f, dsum = 0.f;
    {
        int cnt = min(128, degi);
        for (int q=0;q<cnt;q++){
            float c = sm_e[q];
            acc  += c * h[(size_t)sm_s[q]*HD + t];
            dsum += c;
        }
    }
    // rare chunks beyond 128: recompute (exp applied directly, m known)
    for (int j0=128; j0<degi; j0+=128) {
        __syncthreads();
        int j = j0 + t;
        float ea = 0.f; int s = 0;
        if (j < degi) {
            int e = d_csr[r0+j];
            s = srcArr[e];
            ea = __expf(lrelu(d_as[s] + adi + aE[e]) - m);
        }
        sm_e[t]=ea; sm_s[t]=s;
        __syncthreads();
        int cnt = min(128, degi - j0);
        for (int q=0;q<cnt;q++){
            float c = sm_e[q];
            acc  += c * h[(size_t)sm_s[q]*HD + t];
            dsum += c;
        }
    }
    float eself = __expf(aself - m);
    dsum += eself;
    acc  += eself * h[(size_t)i*HD + t];
    float o = acc/dsum + bias[t];
    size_t idx = (size_t)i*HD + t;
    if (reluSplit) {
        o = fmaxf(o, 0.f);
        __nv_bfloat16 hh = __float2bfloat16(o);
        outH[idx] = hh;
        outL[idx] = __float2bfloat16(o - __bfloat162float(hh));
    } else {
        outF[idx] = o;
    }
}

// ================= decode =================
__global__ void k_decode(const int* __restrict__ srcArr, const int* __restrict__ dstArr,
                         float* __restrict__ out) {
    int w    = blockIdx.x*8 + (threadIdx.x>>5);
    int lane = threadIdx.x & 31;
    if (w >= NE/2) return;
    const float4* z4 = (const float4*)d_z;
    float4 a1 = z4[(size_t)srcArr[w]*32 + lane];
    float4 b1 = z4[(size_t)dstArr[w]*32 + lane];
    float4 a2 = z4[(size_t)srcArr[w+NE/2]*32 + lane];
    float4 b2 = z4[(size_t)dstArr[w+NE/2]*32 + lane];
    float s = a1.x*b1.x + a1.y*b1.y + a1.z*b1.z + a1.w*b1.w
            + a2.x*b2.x + a2.y*b2.y + a2.z*b2.z + a2.w*b2.w;
    #pragma unroll
    for (int o=16;o;o>>=1) s += __shfl_down_sync(~0u,s,o);
    if (lane==0) out[w] = s;
}

// ================= launch =================
extern "C" void kernel_launch(void* const* d_in, const int* in_sizes, int n_in,
                              void* d_out, int out_size) {
    const float* x    = (const float*)d_in[0];
    const int*   ei   = (const int*)  d_in[1];
    const float* ef   = (const float*)d_in[2];
    const float* W1   = (const float*)d_in[4];
    const float* as1  = (const float*)d_in[5];
    const float* ad1  = (const float*)d_in[6];
    const float* We1  = (const float*)d_in[7];
    const float* ae1  = (const float*)d_in[8];
    const float* b1   = (const float*)d_in[9];
    const float* W2   = (const float*)d_in[10];
    const float* as2  = (const float*)d_in[11];
    const float* ad2  = (const float*)d_in[12];
    const float* We2  = (const float*)d_in[13];
    const float* ae2  = (const float*)d_in[14];
    const float* b2   = (const float*)d_in[15];
    const int* src = ei;
    const int* dst = ei + NE;

    float* h;   cudaGetSymbolAddress((void**)&h,   d_h);
    float* z;   cudaGetSymbolAddress((void**)&z,   d_z);
    float* aE1; cudaGetSymbolAddress((void**)&aE1, d_aE1);
    float* aE2; cudaGetSymbolAddress((void**)&aE2, d_aE2);
    float* es1; cudaGetSymbolAddress((void**)&es1, d_esum1);
    float* es2; cudaGetSymbolAddress((void**)&es2, d_esum2);
    __nv_bfloat16 *xh, *xl, *gh, *gl, *wt1h, *wt1l, *wt2h, *wt2l;
    cudaGetSymbolAddress((void**)&xh,  d_xh);
    cudaGetSymbolAddress((void**)&xl,  d_xl);
    cudaGetSymbolAddress((void**)&gh,  d_gh);
    cudaGetSymbolAddress((void**)&gl,  d_gl);
    cudaGetSymbolAddress((void**)&wt1h, d_wt1h);
    cudaGetSymbolAddress((void**)&wt1l, d_wt1l);
    cudaGetSymbolAddress((void**)&wt2h, d_wt2h);
    cudaGetSymbolAddress((void**)&wt2l, d_wt2l);

    k_pre<<<(NN+255)/256, 256>>>(We1, ae1, We2, ae2);
    k_splitX<<<(NN*FIN/4+255)/256, 256>>>(x);
    k_prepW<<<(FIN*HD + HD*HD + 255)/256, 256>>>(W1, W2);
    k_edgedot<<<NE/EPB, EPB>>>(ef, dst);
    k_scan1<<<SCANB, 1024>>>();
    k_scatter<<<(NE+255)/256, 256>>>(dst);

    // layer 1
    k_hgemm<<<GTILES, 256>>>(xh, xl, wt1h, wt1l, h, NN, FIN);
    k_alpha<<<(NN+7)/8, 256>>>(h, as1, ad1);
    k_aggregate<<<NN, 128>>>(h, aE1, es1, src, b1, nullptr, gh, gl, 1);

    // layer 2
    k_hgemm<<<GTILES, 256>>>(gh, gl, wt2h, wt2l, h, NN, HD);
    k_alpha<<<(NN+7)/8, 256>>>(h, as2, ad2);
    k_aggregate<<<NN, 128>>>(h, aE2, es2, src, b2, z, nullptr, nullptr, 0);

    // decode
    k_decode<<<(NE/2+7)/8, 256>>>(src, dst, (float*)d_out);
}